// round 11
// baseline (speedup 1.0000x reference)
#include <cuda_runtime.h>
#include <cuda_bf16.h>
#include <math.h>
#include <stdint.h>

// Problem constants
constexpr int SEQ  = 2048;
constexpr int DM   = 2048;
constexpr int NH   = 16;
constexpr int NKV  = 4;
constexpr int HD   = 128;
constexpr int WIN  = 1024;
constexpr int KVD  = NKV * HD;   // 512
constexpr float CLIPV = 8.0f;
constexpr float SCALE_F = 0.08838834764831845f; // 1/sqrt(128)

// ---------------------------------------------------------------------------
// Static scratch (no allocations allowed)
// ---------------------------------------------------------------------------
__device__ __nv_bfloat16 g_xh[SEQ * DM],  g_xl[SEQ * DM];
__device__ __nv_bfloat16 g_wqh[DM * DM],  g_wql[DM * DM];
__device__ __nv_bfloat16 g_wkh[KVD * DM], g_wkl[KVD * DM];
__device__ __nv_bfloat16 g_wvh[KVD * DM], g_wvl[KVD * DM];
__device__ __nv_bfloat16 g_woh[DM * DM],  g_wol[DM * DM];
__device__ __nv_bfloat16 g_ah[SEQ * DM],  g_al[SEQ * DM];      // attn out hi/lo
__device__ __nv_bfloat16 g_qnh[SEQ * DM], g_qnl[SEQ * DM];     // q normed/roped hi/lo
__device__ __nv_bfloat16 g_knh[SEQ * KVD], g_knl[SEQ * KVD];   // k normed/roped hi/lo
__device__ __nv_bfloat16 g_vnh[SEQ * KVD], g_vnl[SEQ * KVD];   // v hi/lo
__device__ float g_cos[SEQ * 64], g_sin[SEQ * 64];             // rope tables

// ---------------------------------------------------------------------------
// PTX helpers (sm_80+ instruction set — ptxas here targets plain sm_103)
// ---------------------------------------------------------------------------
__device__ __forceinline__ uint32_t smem_u32(const void* p) {
    uint32_t a;
    asm("{ .reg .u64 t; cvta.to.shared.u64 t, %1; cvt.u32.u64 %0, t; }"
        : "=r"(a) : "l"(p));
    return a;
}

__device__ __forceinline__ void cp_async16(uint32_t sp, const void* gp) {
    asm volatile("cp.async.cg.shared.global [%0], [%1], 16;"
                 :: "r"(sp), "l"(gp) : "memory");
}
__device__ __forceinline__ void cp_commit() {
    asm volatile("cp.async.commit_group;" ::: "memory");
}
template <int N>
__device__ __forceinline__ void cp_wait() {
    asm volatile("cp.async.wait_group %0;" :: "n"(N) : "memory");
}

__device__ __forceinline__ void ldmatrix_x4(uint32_t* r, uint32_t addr) {
    asm volatile("ldmatrix.sync.aligned.m8n8.x4.shared.b16 {%0,%1,%2,%3}, [%4];"
                 : "=r"(r[0]), "=r"(r[1]), "=r"(r[2]), "=r"(r[3]) : "r"(addr));
}
__device__ __forceinline__ void ldmatrix_x4_trans(uint32_t* r, uint32_t addr) {
    asm volatile("ldmatrix.sync.aligned.m8n8.x4.trans.shared.b16 {%0,%1,%2,%3}, [%4];"
                 : "=r"(r[0]), "=r"(r[1]), "=r"(r[2]), "=r"(r[3]) : "r"(addr));
}

__device__ __forceinline__ void mma_16816(float* c, const uint32_t* a, const uint32_t* b) {
    asm volatile(
        "mma.sync.aligned.m16n8k16.row.col.f32.bf16.bf16.f32 "
        "{%0,%1,%2,%3}, {%4,%5,%6,%7}, {%8,%9}, {%0,%1,%2,%3};"
        : "+f"(c[0]), "+f"(c[1]), "+f"(c[2]), "+f"(c[3])
        : "r"(a[0]), "r"(a[1]), "r"(a[2]), "r"(a[3]), "r"(b[0]), "r"(b[1]));
}

// ---------------------------------------------------------------------------
// Split fp32 -> (hi, lo) bf16
// ---------------------------------------------------------------------------
__device__ __forceinline__ void split_step(const float* __restrict__ x,
                                           __nv_bfloat16* __restrict__ hi,
                                           __nv_bfloat16* __restrict__ lo, int i) {
    float4 v = ((const float4*)x)[i];
    __nv_bfloat16 h0 = __float2bfloat16(v.x);
    __nv_bfloat16 h1 = __float2bfloat16(v.y);
    __nv_bfloat16 h2 = __float2bfloat16(v.z);
    __nv_bfloat16 h3 = __float2bfloat16(v.w);
    __nv_bfloat16 l0 = __float2bfloat16(v.x - __bfloat162float(h0));
    __nv_bfloat16 l1 = __float2bfloat16(v.y - __bfloat162float(h1));
    __nv_bfloat16 l2 = __float2bfloat16(v.z - __bfloat162float(h2));
    __nv_bfloat16 l3 = __float2bfloat16(v.w - __bfloat162float(h3));
    __nv_bfloat162 hp0 = __halves2bfloat162(h0, h1);
    __nv_bfloat162 hp1 = __halves2bfloat162(h2, h3);
    __nv_bfloat162 lp0 = __halves2bfloat162(l0, l1);
    __nv_bfloat162 lp1 = __halves2bfloat162(l2, l3);
    uint2 hv, lv;
    hv.x = *(uint32_t*)&hp0; hv.y = *(uint32_t*)&hp1;
    lv.x = *(uint32_t*)&lp0; lv.y = *(uint32_t*)&lp1;
    ((uint2*)hi)[i] = hv;
    ((uint2*)lo)[i] = lv;
}

// All four weight splits in one launch. grid = 10240 blocks.
__global__ void split_w_kernel(const float* __restrict__ wq, const float* __restrict__ wk,
                               const float* __restrict__ wv, const float* __restrict__ wo) {
    int b = blockIdx.x;
    if (b < 4096) {
        split_step(wq, g_wqh, g_wql, b * 256 + threadIdx.x);
    } else if (b < 5120) {
        split_step(wk, g_wkh, g_wkl, (b - 4096) * 256 + threadIdx.x);
    } else if (b < 6144) {
        split_step(wv, g_wvh, g_wvl, (b - 5120) * 256 + threadIdx.x);
    } else {
        split_step(wo, g_woh, g_wol, (b - 6144) * 256 + threadIdx.x);
    }
}

// x split + rope tables in one launch. grid = 4608 blocks.
__global__ void prep_x_kernel(const float* __restrict__ x) {
    int b = blockIdx.x;
    if (b < 4096) {
        split_step(x, g_xh, g_xl, b * 256 + threadIdx.x);
    } else {
        int idx = (b - 4096) * 256 + threadIdx.x;   // 0 .. 131071
        int s = idx >> 6, d = idx & 63;
        float inv = powf(500000.0f, -(float)d * (1.0f / 64.0f));
        float sn, cs;
        sincosf((float)s * inv, &sn, &cs);
        g_cos[s * 64 + d] = cs;
        g_sin[s * 64 + d] = sn;
    }
}

// ---------------------------------------------------------------------------
// GEMM core v3: 128x128 tile, 4 warps (128 thr), warp tile 64x64,
// BK=32, 2-stage cp.async pipeline, 3 split MMA sweeps per chunk.
// ---------------------------------------------------------------------------
constexpr int LDSROW = 40;
constexpr int TILE_B = 128 * LDSROW * 2;    // 10240 B
constexpr int CHUNK_B = 4 * TILE_B;         // 40960 B per stage
constexpr int GEMM_SMEM = 2 * CHUNK_B;      // 81920 B

__device__ __forceinline__ void gemm_core(
    const __nv_bfloat16* __restrict__ Ah, const __nv_bfloat16* __restrict__ Al,
    const __nv_bfloat16* __restrict__ Bh, const __nv_bfloat16* __restrict__ Bl,
    int K, float acc[4][8][4], char* dsm) {
    const uint32_t sm0 = smem_u32(dsm);
    const int tid = threadIdx.x;
    const int wid = tid >> 5;
    const int lane = tid & 31;
    const int warp_m = wid & 1;
    const int warp_n = wid >> 1;
    const int NC = K >> 5;

    #pragma unroll
    for (int i = 0; i < 4; i++)
        #pragma unroll
        for (int j = 0; j < 8; j++)
            #pragma unroll
            for (int t = 0; t < 4; t++) acc[i][j][t] = 0.0f;

    auto load_chunk = [&](int c, int s) {
        const int k0 = c << 5;
        const uint32_t b = sm0 + s * CHUNK_B;
        #pragma unroll
        for (int t = 0; t < 4; t++) {
            int idx = tid + t * 128;                 // 0..511
            int r = idx >> 2, g = idx & 3;
            uint32_t off = (uint32_t)(r * LDSROW + g * 8) * 2;
            const size_t ga = (size_t)r * K + k0 + g * 8;
            cp_async16(b + off, Ah + ga);
            cp_async16(b + TILE_B + off, Al + ga);
            cp_async16(b + 2 * TILE_B + off, Bh + ga);
            cp_async16(b + 3 * TILE_B + off, Bl + ga);
        }
    };

    load_chunk(0, 0);
    cp_commit();

    for (int c = 0; c < NC; c++) {
        if (c + 1 < NC) {
            load_chunk(c + 1, (c + 1) & 1);
            cp_commit();
            cp_wait<1>();
        } else {
            cp_wait<0>();
        }
        __syncthreads();

        const uint32_t b = sm0 + (c & 1) * CHUNK_B;
        #pragma unroll
        for (int ks = 0; ks < 2; ks++) {
            const int kc = ks * 16;
            uint32_t ah4[4][4], bh[8][2];
            #pragma unroll
            for (int im = 0; im < 4; im++) {
                int row = warp_m * 64 + im * 16 + (lane & 15);
                int col = kc + ((lane >> 4) << 3);
                ldmatrix_x4(ah4[im], b + (uint32_t)(row * LDSROW + col) * 2);
            }
            #pragma unroll
            for (int ib = 0; ib < 4; ib++) {
                int n = warp_n * 64 + ib * 16 + (lane & 7) + ((lane >> 4) << 3);
                int col = kc + (lane & 8);
                uint32_t r4[4];
                ldmatrix_x4(r4, b + 2 * TILE_B + (uint32_t)(n * LDSROW + col) * 2);
                bh[ib * 2][0] = r4[0]; bh[ib * 2][1] = r4[1];
                bh[ib * 2 + 1][0] = r4[2]; bh[ib * 2 + 1][1] = r4[3];
            }
            // sweep 1: Ah * Bh
            #pragma unroll
            for (int im = 0; im < 4; im++)
                #pragma unroll
                for (int in = 0; in < 8; in++)
                    mma_16816(acc[im][in], ah4[im], bh[in]);
            // sweep 2: Ah * Bl
            {
                uint32_t bl[8][2];
                #pragma unroll
                for (int ib = 0; ib < 4; ib++) {
                    int n = warp_n * 64 + ib * 16 + (lane & 7) + ((lane >> 4) << 3);
                    int col = kc + (lane & 8);
                    uint32_t r4[4];
                    ldmatrix_x4(r4, b + 3 * TILE_B + (uint32_t)(n * LDSROW + col) * 2);
                    bl[ib * 2][0] = r4[0]; bl[ib * 2][1] = r4[1];
                    bl[ib * 2 + 1][0] = r4[2]; bl[ib * 2 + 1][1] = r4[3];
                }
                #pragma unroll
                for (int im = 0; im < 4; im++)
                    #pragma unroll
                    for (int in = 0; in < 8; in++)
                        mma_16816(acc[im][in], ah4[im], bl[in]);
            }
            // sweep 3: Al * Bh
            {
                uint32_t al4[4][4];
                #pragma unroll
                for (int im = 0; im < 4; im++) {
                    int row = warp_m * 64 + im * 16 + (lane & 15);
                    int col = kc + ((lane >> 4) << 3);
                    ldmatrix_x4(al4[im], b + TILE_B + (uint32_t)(row * LDSROW + col) * 2);
                }
                #pragma unroll
                for (int im = 0; im < 4; im++)
                    #pragma unroll
                    for (int in = 0; in < 8; in++)
                        mma_16816(acc[im][in], al4[im], bh[in]);
            }
        }
        __syncthreads();
    }
}

// Epilogue: clip + RMSNorm + RoPE + split-bf16 write (one head per col-block).
__device__ __forceinline__ void epi_norm_rope(
    float acc[4][8][4], char* dsm, int row0, int col0, int LD,
    const float* __restrict__ w,
    __nv_bfloat16* __restrict__ dh, __nv_bfloat16* __restrict__ dl) {
    const int tid = threadIdx.x;
    const int wid = tid >> 5;
    const int lane = tid & 31;
    const int warp_m = wid & 1;
    const int warp_n = wid >> 1;
    float* xs = (float*)dsm;                 // [128][132]
    float* rs = xs + 128 * 132;              // [128][2]

    #pragma unroll
    for (int im = 0; im < 4; im++) {
        #pragma unroll
        for (int half = 0; half < 2; half++) {
            const int rl = warp_m * 64 + im * 16 + (lane >> 2) + half * 8;
            float ss = 0.0f;
            #pragma unroll
            for (int in = 0; in < 8; in++) {
                #pragma unroll
                for (int c = 0; c < 2; c++) {
                    float v = acc[im][in][half * 2 + c];
                    v = fminf(fmaxf(v, -CLIPV), CLIPV);
                    acc[im][in][half * 2 + c] = v;
                    xs[rl * 132 + warp_n * 64 + in * 8 + 2 * (lane & 3) + c] = v;
                    ss += v * v;
                }
            }
            ss += __shfl_xor_sync(0xffffffffu, ss, 1);
            ss += __shfl_xor_sync(0xffffffffu, ss, 2);
            if ((lane & 3) == 0) rs[rl * 2 + warp_n] = ss;
        }
    }
    __syncthreads();

    #pragma unroll
    for (int im = 0; im < 4; im++) {
        #pragma unroll
        for (int half = 0; half < 2; half++) {
            const int rl = warp_m * 64 + im * 16 + (lane >> 2) + half * 8;
            const int pos = row0 + rl;
            const float sum = rs[rl * 2] + rs[rl * 2 + 1];
            const float rsig = rsqrtf(sum * (1.0f / HD) + 1e-6f);
            #pragma unroll
            for (int in = 0; in < 8; in++) {
                const int col = warp_n * 64 + in * 8 + 2 * (lane & 3);
                float o[2];
                #pragma unroll
                for (int c = 0; c < 2; c++) {
                    const int cc = col + c;
                    const float xn = acc[im][in][half * 2 + c] * rsig * w[cc];
                    const float xp = xs[rl * 132 + (cc ^ 64)] * rsig * w[cc ^ 64];
                    const float cs = g_cos[pos * 64 + (cc & 63)];
                    const float sn = g_sin[pos * 64 + (cc & 63)];
                    o[c] = xn * cs + ((cc < 64) ? -xp : xp) * sn;
                }
                __nv_bfloat162 hp = __floats2bfloat162_rn(o[0], o[1]);
                __nv_bfloat162 lp = __floats2bfloat162_rn(o[0] - __low2float(hp),
                                                          o[1] - __high2float(hp));
                const size_t off = (size_t)pos * LD + col0 + col;
                *(__nv_bfloat162*)(dh + off) = hp;
                *(__nv_bfloat162*)(dl + off) = lp;
            }
        }
    }
}

// Epilogue: clip + split-bf16 write (V path).
__device__ __forceinline__ void epi_split(
    float acc[4][8][4], int row0, int col0, int LD,
    __nv_bfloat16* __restrict__ dh, __nv_bfloat16* __restrict__ dl) {
    const int tid = threadIdx.x;
    const int wid = tid >> 5;
    const int lane = tid & 31;
    const int warp_m = wid & 1;
    const int warp_n = wid >> 1;
    #pragma unroll
    for (int im = 0; im < 4; im++) {
        #pragma unroll
        for (int half = 0; half < 2; half++) {
            const int row = row0 + warp_m * 64 + im * 16 + (lane >> 2) + half * 8;
            #pragma unroll
            for (int in = 0; in < 8; in++) {
                const int col = warp_n * 64 + in * 8 + 2 * (lane & 3);
                float o[2];
                #pragma unroll
                for (int c = 0; c < 2; c++)
                    o[c] = fminf(fmaxf(acc[im][in][half * 2 + c], -CLIPV), CLIPV);
                __nv_bfloat162 hp = __floats2bfloat162_rn(o[0], o[1]);
                __nv_bfloat162 lp = __floats2bfloat162_rn(o[0] - __low2float(hp),
                                                          o[1] - __high2float(hp));
                const size_t off = (size_t)row * LD + col0 + col;
                *(__nv_bfloat162*)(dh + off) = hp;
                *(__nv_bfloat162*)(dl + off) = lp;
            }
        }
    }
}

// Fused Q/K/V projection + norm/rope/split epilogues.
// grid (24, 16): x 0-15 -> Q heads, 16-19 -> K heads, 20-23 -> V heads.
__global__ __launch_bounds__(128, 2) void qkv_gemm(const float* __restrict__ qnw,
                                                   const float* __restrict__ knw) {
    extern __shared__ char dsm[];
    const int cx = blockIdx.x;
    const int row0 = blockIdx.y << 7;
    float acc[4][8][4];
    if (cx < 16) {
        const size_t bo = (size_t)(cx << 7) * DM;
        gemm_core(g_xh + (size_t)row0 * DM, g_xl + (size_t)row0 * DM,
                  g_wqh + bo, g_wql + bo, DM, acc, dsm);
        epi_norm_rope(acc, dsm, row0, cx << 7, DM, qnw, g_qnh, g_qnl);
    } else if (cx < 20) {
        const size_t bo = (size_t)((cx - 16) << 7) * DM;
        gemm_core(g_xh + (size_t)row0 * DM, g_xl + (size_t)row0 * DM,
                  g_wkh + bo, g_wkl + bo, DM, acc, dsm);
        epi_norm_rope(acc, dsm, row0, (cx - 16) << 7, KVD, knw, g_knh, g_knl);
    } else {
        const size_t bo = (size_t)((cx - 20) << 7) * DM;
        gemm_core(g_xh + (size_t)row0 * DM, g_xl + (size_t)row0 * DM,
                  g_wvh + bo, g_wvl + bo, DM, acc, dsm);
        epi_split(acc, row0, (cx - 20) << 7, KVD, g_vnh, g_vnl);
    }
}

// Output projection: plain fp32 epilogue.
__global__ __launch_bounds__(128, 2) void out_gemm(float* __restrict__ out) {
    extern __shared__ char dsm[];
    const int row0 = blockIdx.y << 7;
    const int col0 = blockIdx.x << 7;
    float acc[4][8][4];
    gemm_core(g_ah + (size_t)row0 * DM, g_al + (size_t)row0 * DM,
              g_woh + (size_t)col0 * DM, g_wol + (size_t)col0 * DM, DM, acc, dsm);
    const int tid = threadIdx.x;
    const int wid = tid >> 5;
    const int lane = tid & 31;
    const int warp_m = wid & 1;
    const int warp_n = wid >> 1;
    #pragma unroll
    for (int im = 0; im < 4; im++) {
        const int row = row0 + warp_m * 64 + im * 16 + (lane >> 2);
        #pragma unroll
        for (int in = 0; in < 8; in++) {
            const int col = col0 + warp_n * 64 + in * 8 + 2 * (lane & 3);
            *(float2*)(out + (size_t)row * DM + col) =
                make_float2(acc[im][in][0], acc[im][in][1]);
            *(float2*)(out + (size_t)(row + 8) * DM + col) =
                make_float2(acc[im][in][2], acc[im][in][3]);
        }
    }
}

// ---------------------------------------------------------------------------
// Tensor-core flash attention: two GQA heads per CTA (shared K/V),
// double-buffered K/V prefetch, mask-free fast path on interior tiles.
// grid = (8 head-pairs, 32 qtiles rev), 256 threads.
// ---------------------------------------------------------------------------
constexpr int AST = 136;
constexpr int TILE_E = 64 * AST;
constexpr int ATTN_SMEM = 12 * TILE_E * 2;   // 208896 B

__global__ __launch_bounds__(256, 1) void attn_tc(const float* __restrict__ sinks) {
    extern __shared__ __nv_bfloat16 smb[];
    const int g = blockIdx.x;
    const int qt = 31 - (int)blockIdx.y;
    const int q0 = qt << 6;
    const int kvh = g >> 1;
    const int tid = threadIdx.x;
    const int wid = tid >> 5;
    const int lane = tid & 31;
    const int hsel = wid >> 2;
    const int wq = wid & 3;
    const int h = g * 2 + hsel;

    __nv_bfloat16* Qh = smb + hsel * 2 * TILE_E;
    __nv_bfloat16* Ql = Qh + TILE_E;

    for (int idx = tid; idx < 2048; idx += 256) {
        int hd = idx >> 10;
        int rem = idx & 1023;
        int r = rem >> 4, c = rem & 15;
        const size_t go = (size_t)(q0 + r) * DM + (g * 2 + hd) * HD + c * 8;
        cp_async16(smem_u32(smb + hd * 2 * TILE_E + r * AST + c * 8), g_qnh + go);
        cp_async16(smem_u32(smb + (hd * 2 + 1) * TILE_E + r * AST + c * 8), g_qnl + go);
    }
    cp_commit();

    auto load_kv = [&](int kt, int b) {
        const int k0 = kt << 6;
        __nv_bfloat16* Khp = smb + (4 + 2 * b) * TILE_E;
        __nv_bfloat16* Klp = Khp + TILE_E;
        __nv_bfloat16* Vhp = smb + (8 + 2 * b) * TILE_E;
        __nv_bfloat16* Vlp = Vhp + TILE_E;
        for (int idx = tid; idx < 1024; idx += 256) {
            int r = idx >> 4, c = idx & 15;
            const size_t go = (size_t)(k0 + r) * KVD + kvh * HD + c * 8;
            cp_async16(smem_u32(Khp + r * AST + c * 8), g_knh + go);
            cp_async16(smem_u32(Klp + r * AST + c * 8), g_knl + go);
            cp_async16(smem_u32(Vhp + r * AST + c * 8), g_vnh + go);
            cp_async16(smem_u32(Vlp + r * AST + c * 8), g_vnl + go);
        }
    };

    int lo = q0 - WIN + 1;
    if (lo < 0) lo = 0;
    const int kt_lo = lo >> 6;
    load_kv(kt_lo, 0);
    cp_commit();

    float m[2] = {-1e30f, -1e30f}, lsum[2] = {0.0f, 0.0f};
    float acc_o[16][4];
    #pragma unroll
    for (int n = 0; n < 16; n++)
        #pragma unroll
        for (int t = 0; t < 4; t++) acc_o[n][t] = 0.0f;

    const int r0 = lane >> 2;

    for (int kt = kt_lo; kt <= qt; kt++) {
        const int b = (kt - kt_lo) & 1;
        const int k0 = kt << 6;
        const bool need_mask = (kt == qt) || (k0 < lo);
        if (kt < qt) {
            load_kv(kt + 1, b ^ 1);
            cp_commit();
            cp_wait<1>();
        } else {
            cp_wait<0>();
        }
        __syncthreads();

        __nv_bfloat16* Kh = smb + (4 + 2 * b) * TILE_E;
        __nv_bfloat16* Kl = Kh + TILE_E;
        __nv_bfloat16* Vh = smb + (8 + 2 * b) * TILE_E;
        __nv_bfloat16* Vl = Vh + TILE_E;

        // ---- S = Q K^T (3 split passes) ----
        float acc_s[8][4];
        #pragma unroll
        for (int j = 0; j < 8; j++)
            #pragma unroll
            for (int t = 0; t < 4; t++) acc_s[j][t] = 0.0f;

        #pragma unroll
        for (int ks = 0; ks < 8; ks++) {
            uint32_t ah4[4], al4[4];
            const int qrow = wq * 16 + (lane & 15);
            const int qcol = ks * 16 + ((lane >> 4) << 3);
            ldmatrix_x4(ah4, smem_u32(Qh + qrow * AST + qcol));
            ldmatrix_x4(al4, smem_u32(Ql + qrow * AST + qcol));
            #pragma unroll
            for (int np = 0; np < 4; np++) {
                const int n = np * 16 + (lane & 7) + ((lane >> 4) << 3);
                const int col = ks * 16 + (lane & 8);
                uint32_t bh4[4], bl4[4];
                ldmatrix_x4(bh4, smem_u32(Kh + n * AST + col));
                ldmatrix_x4(bl4, smem_u32(Kl + n * AST + col));
                mma_16816(acc_s[2 * np],     ah4, bh4);
                mma_16816(acc_s[2 * np],     al4, bh4);
                mma_16816(acc_s[2 * np],     ah4, bl4);
                mma_16816(acc_s[2 * np + 1], ah4, bh4 + 2);
                mma_16816(acc_s[2 * np + 1], al4, bh4 + 2);
                mma_16816(acc_s[2 * np + 1], ah4, bl4 + 2);
            }
        }

        // ---- mask + online softmax ----
        #pragma unroll
        for (int half = 0; half < 2; half++) {
            const int qi = q0 + wq * 16 + r0 + half * 8;
            float rm = -1e30f;
            if (need_mask) {
                #pragma unroll
                for (int j = 0; j < 8; j++) {
                    #pragma unroll
                    for (int c = 0; c < 2; c++) {
                        const int ki = k0 + j * 8 + 2 * (lane & 3) + c;
                        float v = acc_s[j][half * 2 + c];
                        v = (ki <= qi && ki > qi - WIN) ? v * SCALE_F : -1e30f;
                        acc_s[j][half * 2 + c] = v;
                        rm = fmaxf(rm, v);
                    }
                }
            } else {
                #pragma unroll
                for (int j = 0; j < 8; j++) {
                    #pragma unroll
                    for (int c = 0; c < 2; c++) {
                        float v = acc_s[j][half * 2 + c] * SCALE_F;
                        acc_s[j][half * 2 + c] = v;
                        rm = fmaxf(rm, v);
                    }
                }
            }
            rm = fmaxf(rm, __shfl_xor_sync(0xffffffffu, rm, 1));
            rm = fmaxf(rm, __shfl_xor_sync(0xffffffffu, rm, 2));
            const float nm = fmaxf(m[half], rm);
            const float sc = __expf(m[half] - nm);
            float rs = 0.0f;
            #pragma unroll
            for (int j = 0; j < 8; j++) {
                #pragma unroll
                for (int c = 0; c < 2; c++) {
                    float v = acc_s[j][half * 2 + c];
                    float p = (v > -1e29f) ? __expf(v - nm) : 0.0f;
                    acc_s[j][half * 2 + c] = p;
                    rs += p;
                }
            }
            rs += __shfl_xor_sync(0xffffffffu, rs, 1);
            rs += __shfl_xor_sync(0xffffffffu, rs, 2);
            lsum[half] = lsum[half] * sc + rs;
            m[half] = nm;
            #pragma unroll
            for (int n = 0; n < 16; n++) {
                acc_o[n][half * 2]     *= sc;
                acc_o[n][half * 2 + 1] *= sc;
            }
        }

        // ---- repack P into A fragments (hi + lo) ----
        uint32_t aPh[4][4], aPl[4][4];
        #pragma unroll
        for (int kk = 0; kk < 4; kk++) {
            #pragma unroll
            for (int t = 0; t < 4; t++) {
                const int j = 2 * kk + (t >> 1);
                const int c0 = (t & 1) * 2;
                const float p0 = acc_s[j][c0], p1 = acc_s[j][c0 + 1];
                __nv_bfloat162 hp = __floats2bfloat162_rn(p0, p1);
                __nv_bfloat162 lp = __floats2bfloat162_rn(p0 - __low2float(hp),
                                                          p1 - __high2float(hp));
                aPh[kk][t] = *(uint32_t*)&hp;
                aPl[kk][t] = *(uint32_t*)&lp;
            }
        }

        // ---- O += P V (3 split passes) ----
        #pragma unroll
        for (int kk = 0; kk < 4; kk++) {
            const int vrow = kk * 16 + (lane & 15);
            const int vcol = (lane >> 4) << 3;
            #pragma unroll
            for (int np = 0; np < 8; np++) {
                uint32_t bh4[4], bl4[4];
                ldmatrix_x4_trans(bh4, smem_u32(Vh + vrow * AST + np * 16 + vcol));
                mma_16816(acc_o[2 * np],     aPh[kk], bh4);
                mma_16816(acc_o[2 * np + 1], aPh[kk], bh4 + 2);
                mma_16816(acc_o[2 * np],     aPl[kk], bh4);
                mma_16816(acc_o[2 * np + 1], aPl[kk], bh4 + 2);
                ldmatrix_x4_trans(bl4, smem_u32(Vl + vrow * AST + np * 16 + vcol));
                mma_16816(acc_o[2 * np],     aPh[kk], bl4);
                mma_16816(acc_o[2 * np + 1], aPh[kk], bl4 + 2);
            }
        }
        __syncthreads();
    }

    // ---- sink fold + write split-bf16 output ----
    const float snk = sinks[h];
    #pragma unroll
    for (int half = 0; half < 2; half++) {
        const float M = fmaxf(m[half], snk);
        const float denom = lsum[half] * __expf(m[half] - M) + __expf(snk - M);
        const float ns = __expf(m[half] - M) / denom;
        const int row = q0 + wq * 16 + r0 + half * 8;
        #pragma unroll
        for (int n = 0; n < 16; n++) {
            const float v0 = acc_o[n][half * 2] * ns;
            const float v1 = acc_o[n][half * 2 + 1] * ns;
            __nv_bfloat162 hp = __floats2bfloat162_rn(v0, v1);
            __nv_bfloat162 lp = __floats2bfloat162_rn(v0 - __low2float(hp),
                                                      v1 - __high2float(hp));
            const size_t off = (size_t)row * DM + h * HD + n * 8 + 2 * (lane & 3);
            *(__nv_bfloat162*)(g_ah + off) = hp;
            *(__nv_bfloat162*)(g_al + off) = lp;
        }
    }
}

// ---------------------------------------------------------------------------
// Launch. attn_tc at my-launch idx 3 gets ncu-profiled.
// ---------------------------------------------------------------------------
extern "C" void kernel_launch(void* const* d_in, const int* in_sizes, int n_in,
                              void* d_out, int out_size) {
    const float* x     = (const float*)d_in[0];
    const float* w_q   = (const float*)d_in[1];
    const float* w_k   = (const float*)d_in[2];
    const float* w_v   = (const float*)d_in[3];
    const float* w_out = (const float*)d_in[4];
    const float* qnw   = (const float*)d_in[5];
    const float* knw   = (const float*)d_in[6];
    const float* sinks = (const float*)d_in[7];
    float* out = (float*)d_out;

    cudaFuncSetAttribute(qkv_gemm, cudaFuncAttributeMaxDynamicSharedMemorySize, GEMM_SMEM);
    cudaFuncSetAttribute(out_gemm, cudaFuncAttributeMaxDynamicSharedMemorySize, GEMM_SMEM);
    cudaFuncSetAttribute(attn_tc,  cudaFuncAttributeMaxDynamicSharedMemorySize, ATTN_SMEM);

    // 0: weight splits
    split_w_kernel<<<10240, 256>>>(w_q, w_k, w_v, w_out);
    // 1: x split + rope tables
    prep_x_kernel<<<4608, 256>>>(x);
    // 2: fused Q/K/V projection + clip + RMSNorm + RoPE + split epilogues
    qkv_gemm<<<dim3(24, 16), 128, GEMM_SMEM>>>(qnw, knw);
    // 3: windowed flash attention + sink  (profiled slot)
    attn_tc<<<dim3(8, 32), 256, ATTN_SMEM>>>(sinks);
    // 4: output projection
    out_gemm<<<dim3(16, 16), 128, GEMM_SMEM>>>(out);
}

// round 12
// speedup vs baseline: 1.1482x; 1.1482x over previous
#include <cuda_runtime.h>
#include <cuda_fp16.h>
#include <math.h>
#include <stdint.h>

// Problem constants
constexpr int SEQ  = 2048;
constexpr int DM   = 2048;
constexpr int NH   = 16;
constexpr int NKV  = 4;
constexpr int HD   = 128;
constexpr int WIN  = 1024;
constexpr int KVD  = NKV * HD;   // 512
constexpr float CLIPV = 8.0f;
constexpr float SCALE_F = 0.08838834764831845f; // 1/sqrt(128)

// ---------------------------------------------------------------------------
// Static scratch (no allocations allowed)
// ---------------------------------------------------------------------------
__device__ __half g_xh[SEQ * DM],  g_xl[SEQ * DM];
__device__ __half g_wqh[DM * DM];            // weight lo never needed (2-pass)
__device__ __half g_wkh[KVD * DM];
__device__ __half g_wvh[KVD * DM];
__device__ __half g_woh[DM * DM];
__device__ __half g_ah[SEQ * DM],  g_al[SEQ * DM];      // attn out hi/lo
__device__ __half g_qnh[SEQ * DM], g_qnl[SEQ * DM];     // q normed/roped hi/lo
__device__ __half g_knh[SEQ * KVD], g_knl[SEQ * KVD];   // k normed/roped hi/lo
__device__ __half g_vnh[SEQ * KVD], g_vnl[SEQ * KVD];   // v hi/lo
__device__ float g_cos[SEQ * 64], g_sin[SEQ * 64];      // rope tables

// ---------------------------------------------------------------------------
// PTX helpers (sm_80+ instruction set — ptxas here targets plain sm_103)
// ---------------------------------------------------------------------------
__device__ __forceinline__ uint32_t smem_u32(const void* p) {
    uint32_t a;
    asm("{ .reg .u64 t; cvta.to.shared.u64 t, %1; cvt.u32.u64 %0, t; }"
        : "=r"(a) : "l"(p));
    return a;
}

__device__ __forceinline__ void cp_async16(uint32_t sp, const void* gp) {
    asm volatile("cp.async.cg.shared.global [%0], [%1], 16;"
                 :: "r"(sp), "l"(gp) : "memory");
}
__device__ __forceinline__ void cp_commit() {
    asm volatile("cp.async.commit_group;" ::: "memory");
}
template <int N>
__device__ __forceinline__ void cp_wait() {
    asm volatile("cp.async.wait_group %0;" :: "n"(N) : "memory");
}

__device__ __forceinline__ void ldmatrix_x4(uint32_t* r, uint32_t addr) {
    asm volatile("ldmatrix.sync.aligned.m8n8.x4.shared.b16 {%0,%1,%2,%3}, [%4];"
                 : "=r"(r[0]), "=r"(r[1]), "=r"(r[2]), "=r"(r[3]) : "r"(addr));
}
__device__ __forceinline__ void ldmatrix_x4_trans(uint32_t* r, uint32_t addr) {
    asm volatile("ldmatrix.sync.aligned.m8n8.x4.trans.shared.b16 {%0,%1,%2,%3}, [%4];"
                 : "=r"(r[0]), "=r"(r[1]), "=r"(r[2]), "=r"(r[3]) : "r"(addr));
}

__device__ __forceinline__ void mma_16816(float* c, const uint32_t* a, const uint32_t* b) {
    asm volatile(
        "mma.sync.aligned.m16n8k16.row.col.f32.f16.f16.f32 "
        "{%0,%1,%2,%3}, {%4,%5,%6,%7}, {%8,%9}, {%0,%1,%2,%3};"
        : "+f"(c[0]), "+f"(c[1]), "+f"(c[2]), "+f"(c[3])
        : "r"(a[0]), "r"(a[1]), "r"(a[2]), "r"(a[3]), "r"(b[0]), "r"(b[1]));
}

__device__ __forceinline__ uint32_t pack_h2(float a, float b) {
    __half2 h = __floats2half2_rn(a, b);
    return *(uint32_t*)&h;
}

// ---------------------------------------------------------------------------
// Splits fp32 -> fp16 (hi[, lo])
// ---------------------------------------------------------------------------
__device__ __forceinline__ void split_hl(const float* __restrict__ x,
                                         __half* __restrict__ hi,
                                         __half* __restrict__ lo, int i) {
    float4 v = ((const float4*)x)[i];
    __half h0 = __float2half_rn(v.x), h1 = __float2half_rn(v.y);
    __half h2 = __float2half_rn(v.z), h3 = __float2half_rn(v.w);
    __half l0 = __float2half_rn(v.x - __half2float(h0));
    __half l1 = __float2half_rn(v.y - __half2float(h1));
    __half l2 = __float2half_rn(v.z - __half2float(h2));
    __half l3 = __float2half_rn(v.w - __half2float(h3));
    __half2 hp0 = __halves2half2(h0, h1), hp1 = __halves2half2(h2, h3);
    __half2 lp0 = __halves2half2(l0, l1), lp1 = __halves2half2(l2, l3);
    uint2 hv, lv;
    hv.x = *(uint32_t*)&hp0; hv.y = *(uint32_t*)&hp1;
    lv.x = *(uint32_t*)&lp0; lv.y = *(uint32_t*)&lp1;
    ((uint2*)hi)[i] = hv;
    ((uint2*)lo)[i] = lv;
}

__device__ __forceinline__ void split_h(const float* __restrict__ x,
                                        __half* __restrict__ hi, int i) {
    float4 v = ((const float4*)x)[i];
    __half2 hp0 = __floats2half2_rn(v.x, v.y);
    __half2 hp1 = __floats2half2_rn(v.z, v.w);
    uint2 hv;
    hv.x = *(uint32_t*)&hp0; hv.y = *(uint32_t*)&hp1;
    ((uint2*)hi)[i] = hv;
}

// Weight splits (hi only). grid = 10240 blocks.
__global__ void split_w_kernel(const float* __restrict__ wq, const float* __restrict__ wk,
                               const float* __restrict__ wv, const float* __restrict__ wo) {
    int b = blockIdx.x;
    if (b < 4096) {
        split_h(wq, g_wqh, b * 256 + threadIdx.x);
    } else if (b < 5120) {
        split_h(wk, g_wkh, (b - 4096) * 256 + threadIdx.x);
    } else if (b < 6144) {
        split_h(wv, g_wvh, (b - 5120) * 256 + threadIdx.x);
    } else {
        split_h(wo, g_woh, (b - 6144) * 256 + threadIdx.x);
    }
}

// x split (hi/lo) + rope tables in one launch. grid = 4608 blocks.
__global__ void prep_x_kernel(const float* __restrict__ x) {
    int b = blockIdx.x;
    if (b < 4096) {
        split_hl(x, g_xh, g_xl, b * 256 + threadIdx.x);
    } else {
        int idx = (b - 4096) * 256 + threadIdx.x;
        int s = idx >> 6, d = idx & 63;
        float inv = powf(500000.0f, -(float)d * (1.0f / 64.0f));
        float sn, cs;
        sincosf((float)s * inv, &sn, &cs);
        g_cos[s * 64 + d] = cs;
        g_sin[s * 64 + d] = sn;
    }
}

// ---------------------------------------------------------------------------
// GEMM core (fp16 2-pass): 128x128 tile, 256 thr (8 warps, warp tile 64x32),
// BK=32, 2-stage cp.async pipeline. Per stage: Ah | Al | Bh (3 tiles).
// ---------------------------------------------------------------------------
constexpr int LDSROW = 40;
constexpr int TILE_B = 128 * LDSROW * 2;    // 10240 B
constexpr int CHUNK_B = 3 * TILE_B;         // 30720 B per stage
constexpr int GEMM_SMEM = 69632;            // max(2*CHUNK_B, epi: 128*132*4 + 2048)

__device__ __forceinline__ void gemm_core(
    const __half* __restrict__ Ah, const __half* __restrict__ Al,
    const __half* __restrict__ Bh,
    int K, float acc[4][4][4], char* dsm) {
    const uint32_t sm0 = smem_u32(dsm);
    const int tid = threadIdx.x;
    const int wid = tid >> 5;
    const int lane = tid & 31;
    const int warp_m = wid & 1;
    const int warp_n = wid >> 1;
    const int NC = K >> 5;

    #pragma unroll
    for (int i = 0; i < 4; i++)
        #pragma unroll
        for (int j = 0; j < 4; j++)
            #pragma unroll
            for (int t = 0; t < 4; t++) acc[i][j][t] = 0.0f;

    auto load_chunk = [&](int c, int s) {
        const int k0 = c << 5;
        const uint32_t b = sm0 + s * CHUNK_B;
        #pragma unroll
        for (int t = 0; t < 2; t++) {
            int idx = tid + t * 256;
            int r = idx >> 2, g = idx & 3;
            uint32_t off = (uint32_t)(r * LDSROW + g * 8) * 2;
            const size_t ga = (size_t)r * K + k0 + g * 8;
            cp_async16(b + off, Ah + ga);
            cp_async16(b + TILE_B + off, Al + ga);
            cp_async16(b + 2 * TILE_B + off, Bh + ga);
        }
    };

    load_chunk(0, 0);
    cp_commit();

    for (int c = 0; c < NC; c++) {
        if (c + 1 < NC) {
            load_chunk(c + 1, (c + 1) & 1);
            cp_commit();
            cp_wait<1>();
        } else {
            cp_wait<0>();
        }
        __syncthreads();

        const uint32_t b = sm0 + (c & 1) * CHUNK_B;
        #pragma unroll
        for (int ks = 0; ks < 2; ks++) {
            const int kc = ks * 16;
            uint32_t ah4[4][4], bh[4][2];
            #pragma unroll
            for (int im = 0; im < 4; im++) {
                int row = warp_m * 64 + im * 16 + (lane & 15);
                int col = kc + ((lane >> 4) << 3);
                ldmatrix_x4(ah4[im], b + (uint32_t)(row * LDSROW + col) * 2);
            }
            #pragma unroll
            for (int ib = 0; ib < 2; ib++) {
                int n = warp_n * 32 + ib * 16 + (lane & 7) + ((lane >> 4) << 3);
                int col = kc + (lane & 8);
                uint32_t r4[4];
                ldmatrix_x4(r4, b + 2 * TILE_B + (uint32_t)(n * LDSROW + col) * 2);
                bh[ib * 2][0] = r4[0]; bh[ib * 2][1] = r4[1];
                bh[ib * 2 + 1][0] = r4[2]; bh[ib * 2 + 1][1] = r4[3];
            }
            // sweep 1: Ah * Bh
            #pragma unroll
            for (int im = 0; im < 4; im++)
                #pragma unroll
                for (int in = 0; in < 4; in++)
                    mma_16816(acc[im][in], ah4[im], bh[in]);
            // sweep 2: Al * Bh
            #pragma unroll
            for (int im = 0; im < 4; im++) {
                int row = warp_m * 64 + im * 16 + (lane & 15);
                int col = kc + ((lane >> 4) << 3);
                ldmatrix_x4(ah4[im], b + TILE_B + (uint32_t)(row * LDSROW + col) * 2);
            }
            #pragma unroll
            for (int im = 0; im < 4; im++)
                #pragma unroll
                for (int in = 0; in < 4; in++)
                    mma_16816(acc[im][in], ah4[im], bh[in]);
        }
        __syncthreads();
    }
}

// Epilogue: clip + RMSNorm + RoPE + split-fp16 write (one head per col-block).
__device__ __forceinline__ void epi_norm_rope(
    float acc[4][4][4], char* dsm, int row0, int col0, int LD,
    const float* __restrict__ w,
    __half* __restrict__ dh, __half* __restrict__ dl) {
    const int tid = threadIdx.x;
    const int wid = tid >> 5;
    const int lane = tid & 31;
    const int warp_m = wid & 1;
    const int warp_n = wid >> 1;
    float* xs = (float*)dsm;                 // [128][132]
    float* rs = xs + 128 * 132;              // [128][4]

    #pragma unroll
    for (int im = 0; im < 4; im++) {
        #pragma unroll
        for (int half_ = 0; half_ < 2; half_++) {
            const int rl = warp_m * 64 + im * 16 + (lane >> 2) + half_ * 8;
            float ss = 0.0f;
            #pragma unroll
            for (int in = 0; in < 4; in++) {
                #pragma unroll
                for (int c = 0; c < 2; c++) {
                    float v = acc[im][in][half_ * 2 + c];
                    v = fminf(fmaxf(v, -CLIPV), CLIPV);
                    acc[im][in][half_ * 2 + c] = v;
                    xs[rl * 132 + warp_n * 32 + in * 8 + 2 * (lane & 3) + c] = v;
                    ss += v * v;
                }
            }
            ss += __shfl_xor_sync(0xffffffffu, ss, 1);
            ss += __shfl_xor_sync(0xffffffffu, ss, 2);
            if ((lane & 3) == 0) rs[rl * 4 + warp_n] = ss;
        }
    }
    __syncthreads();

    #pragma unroll
    for (int im = 0; im < 4; im++) {
        #pragma unroll
        for (int half_ = 0; half_ < 2; half_++) {
            const int rl = warp_m * 64 + im * 16 + (lane >> 2) + half_ * 8;
            const int pos = row0 + rl;
            const float sum = rs[rl * 4] + rs[rl * 4 + 1] + rs[rl * 4 + 2] + rs[rl * 4 + 3];
            const float rsig = rsqrtf(sum * (1.0f / HD) + 1e-6f);
            #pragma unroll
            for (int in = 0; in < 4; in++) {
                const int col = warp_n * 32 + in * 8 + 2 * (lane & 3);
                float o[2];
                #pragma unroll
                for (int c = 0; c < 2; c++) {
                    const int cc = col + c;
                    const float xn = acc[im][in][half_ * 2 + c] * rsig * w[cc];
                    const float xp = xs[rl * 132 + (cc ^ 64)] * rsig * w[cc ^ 64];
                    const float cs = g_cos[pos * 64 + (cc & 63)];
                    const float sn = g_sin[pos * 64 + (cc & 63)];
                    o[c] = xn * cs + ((cc < 64) ? -xp : xp) * sn;
                }
                __half2 hp = __floats2half2_rn(o[0], o[1]);
                __half2 lp = __floats2half2_rn(o[0] - __half2float(__low2half(hp)),
                                               o[1] - __half2float(__high2half(hp)));
                const size_t off = (size_t)pos * LD + col0 + col;
                *(__half2*)(dh + off) = hp;
                *(__half2*)(dl + off) = lp;
            }
        }
    }
}

// Epilogue: clip + split-fp16 write (V path).
__device__ __forceinline__ void epi_split(
    float acc[4][4][4], int row0, int col0, int LD,
    __half* __restrict__ dh, __half* __restrict__ dl) {
    const int tid = threadIdx.x;
    const int wid = tid >> 5;
    const int lane = tid & 31;
    const int warp_m = wid & 1;
    const int warp_n = wid >> 1;
    #pragma unroll
    for (int im = 0; im < 4; im++) {
        #pragma unroll
        for (int half_ = 0; half_ < 2; half_++) {
            const int row = row0 + warp_m * 64 + im * 16 + (lane >> 2) + half_ * 8;
            #pragma unroll
            for (int in = 0; in < 4; in++) {
                const int col = warp_n * 32 + in * 8 + 2 * (lane & 3);
                float o[2];
                #pragma unroll
                for (int c = 0; c < 2; c++)
                    o[c] = fminf(fmaxf(acc[im][in][half_ * 2 + c], -CLIPV), CLIPV);
                __half2 hp = __floats2half2_rn(o[0], o[1]);
                __half2 lp = __floats2half2_rn(o[0] - __half2float(__low2half(hp)),
                                               o[1] - __half2float(__high2half(hp)));
                const size_t off = (size_t)row * LD + col0 + col;
                *(__half2*)(dh + off) = hp;
                *(__half2*)(dl + off) = lp;
            }
        }
    }
}

// Fused Q/K/V projection + norm/rope/split epilogues.
// grid (24, 16): x 0-15 -> Q heads, 16-19 -> K heads, 20-23 -> V heads.
__global__ __launch_bounds__(256, 2) void qkv_gemm(const float* __restrict__ qnw,
                                                   const float* __restrict__ knw) {
    extern __shared__ char dsm[];
    const int cx = blockIdx.x;
    const int row0 = blockIdx.y << 7;
    float acc[4][4][4];
    if (cx < 16) {
        const size_t bo = (size_t)(cx << 7) * DM;
        gemm_core(g_xh + (size_t)row0 * DM, g_xl + (size_t)row0 * DM,
                  g_wqh + bo, DM, acc, dsm);
        epi_norm_rope(acc, dsm, row0, cx << 7, DM, qnw, g_qnh, g_qnl);
    } else if (cx < 20) {
        const size_t bo = (size_t)((cx - 16) << 7) * DM;
        gemm_core(g_xh + (size_t)row0 * DM, g_xl + (size_t)row0 * DM,
                  g_wkh + bo, DM, acc, dsm);
        epi_norm_rope(acc, dsm, row0, (cx - 16) << 7, KVD, knw, g_knh, g_knl);
    } else {
        const size_t bo = (size_t)((cx - 20) << 7) * DM;
        gemm_core(g_xh + (size_t)row0 * DM, g_xl + (size_t)row0 * DM,
                  g_wvh + bo, DM, acc, dsm);
        epi_split(acc, row0, (cx - 20) << 7, KVD, g_vnh, g_vnl);
    }
}

// Output projection: plain fp32 epilogue.
__global__ __launch_bounds__(256, 2) void out_gemm(float* __restrict__ out) {
    extern __shared__ char dsm[];
    const int row0 = blockIdx.y << 7;
    const int col0 = blockIdx.x << 7;
    float acc[4][4][4];
    gemm_core(g_ah + (size_t)row0 * DM, g_al + (size_t)row0 * DM,
              g_woh + (size_t)col0 * DM, DM, acc, dsm);
    const int tid = threadIdx.x;
    const int wid = tid >> 5;
    const int lane = tid & 31;
    const int warp_m = wid & 1;
    const int warp_n = wid >> 1;
    #pragma unroll
    for (int im = 0; im < 4; im++) {
        const int row = row0 + warp_m * 64 + im * 16 + (lane >> 2);
        #pragma unroll
        for (int in = 0; in < 4; in++) {
            const int col = col0 + warp_n * 32 + in * 8 + 2 * (lane & 3);
            *(float2*)(out + (size_t)row * DM + col) =
                make_float2(acc[im][in][0], acc[im][in][1]);
            *(float2*)(out + (size_t)(row + 8) * DM + col) =
                make_float2(acc[im][in][2], acc[im][in][3]);
        }
    }
}

// ---------------------------------------------------------------------------
// Tensor-core flash attention (fp16): two GQA heads per CTA (shared K/V),
// double-buffered K/V prefetch, QK 3-pass, PV 2-pass (P single fp16).
// grid = (8 head-pairs, 32 qtiles rev), 256 threads.
// ---------------------------------------------------------------------------
constexpr int AST = 136;
constexpr int TILE_E = 64 * AST;
constexpr int ATTN_SMEM = 12 * TILE_E * 2;   // 208896 B

__global__ __launch_bounds__(256, 1) void attn_tc(const float* __restrict__ sinks) {
    extern __shared__ __half smb[];
    const int g = blockIdx.x;
    const int qt = 31 - (int)blockIdx.y;
    const int q0 = qt << 6;
    const int kvh = g >> 1;
    const int tid = threadIdx.x;
    const int wid = tid >> 5;
    const int lane = tid & 31;
    const int hsel = wid >> 2;
    const int wq = wid & 3;
    const int h = g * 2 + hsel;

    __half* Qh = smb + hsel * 2 * TILE_E;
    __half* Ql = Qh + TILE_E;

    for (int idx = tid; idx < 2048; idx += 256) {
        int hd = idx >> 10;
        int rem = idx & 1023;
        int r = rem >> 4, c = rem & 15;
        const size_t go = (size_t)(q0 + r) * DM + (g * 2 + hd) * HD + c * 8;
        cp_async16(smem_u32(smb + hd * 2 * TILE_E + r * AST + c * 8), g_qnh + go);
        cp_async16(smem_u32(smb + (hd * 2 + 1) * TILE_E + r * AST + c * 8), g_qnl + go);
    }
    cp_commit();

    auto load_kv = [&](int kt, int b) {
        const int k0 = kt << 6;
        __half* Khp = smb + (4 + 2 * b) * TILE_E;
        __half* Klp = Khp + TILE_E;
        __half* Vhp = smb + (8 + 2 * b) * TILE_E;
        __half* Vlp = Vhp + TILE_E;
        for (int idx = tid; idx < 1024; idx += 256) {
            int r = idx >> 4, c = idx & 15;
            const size_t go = (size_t)(k0 + r) * KVD + kvh * HD + c * 8;
            cp_async16(smem_u32(Khp + r * AST + c * 8), g_knh + go);
            cp_async16(smem_u32(Klp + r * AST + c * 8), g_knl + go);
            cp_async16(smem_u32(Vhp + r * AST + c * 8), g_vnh + go);
            cp_async16(smem_u32(Vlp + r * AST + c * 8), g_vnl + go);
        }
    };

    int lo = q0 - WIN + 1;
    if (lo < 0) lo = 0;
    const int kt_lo = lo >> 6;
    load_kv(kt_lo, 0);
    cp_commit();

    float m[2] = {-1e30f, -1e30f}, lsum[2] = {0.0f, 0.0f};
    float acc_o[16][4];
    #pragma unroll
    for (int n = 0; n < 16; n++)
        #pragma unroll
        for (int t = 0; t < 4; t++) acc_o[n][t] = 0.0f;

    const int r0 = lane >> 2;

    for (int kt = kt_lo; kt <= qt; kt++) {
        const int b = (kt - kt_lo) & 1;
        const int k0 = kt << 6;
        const bool need_mask = (kt == qt) || (k0 < lo);
        if (kt < qt) {
            load_kv(kt + 1, b ^ 1);
            cp_commit();
            cp_wait<1>();
        } else {
            cp_wait<0>();
        }
        __syncthreads();

        __half* Kh = smb + (4 + 2 * b) * TILE_E;
        __half* Kl = Kh + TILE_E;
        __half* Vh = smb + (8 + 2 * b) * TILE_E;
        __half* Vl = Vh + TILE_E;

        // ---- S = Q K^T (3 split passes) ----
        float acc_s[8][4];
        #pragma unroll
        for (int j = 0; j < 8; j++)
            #pragma unroll
            for (int t = 0; t < 4; t++) acc_s[j][t] = 0.0f;

        #pragma unroll
        for (int ks = 0; ks < 8; ks++) {
            uint32_t ah4[4], al4[4];
            const int qrow = wq * 16 + (lane & 15);
            const int qcol = ks * 16 + ((lane >> 4) << 3);
            ldmatrix_x4(ah4, smem_u32(Qh + qrow * AST + qcol));
            ldmatrix_x4(al4, smem_u32(Ql + qrow * AST + qcol));
            #pragma unroll
            for (int np = 0; np < 4; np++) {
                const int n = np * 16 + (lane & 7) + ((lane >> 4) << 3);
                const int col = ks * 16 + (lane & 8);
                uint32_t bh4[4], bl4[4];
                ldmatrix_x4(bh4, smem_u32(Kh + n * AST + col));
                ldmatrix_x4(bl4, smem_u32(Kl + n * AST + col));
                mma_16816(acc_s[2 * np],     ah4, bh4);
                mma_16816(acc_s[2 * np],     al4, bh4);
                mma_16816(acc_s[2 * np],     ah4, bl4);
                mma_16816(acc_s[2 * np + 1], ah4, bh4 + 2);
                mma_16816(acc_s[2 * np + 1], al4, bh4 + 2);
                mma_16816(acc_s[2 * np + 1], ah4, bl4 + 2);
            }
        }

        // ---- mask + online softmax ----
        #pragma unroll
        for (int half_ = 0; half_ < 2; half_++) {
            const int qi = q0 + wq * 16 + r0 + half_ * 8;
            float rm = -1e30f;
            if (need_mask) {
                #pragma unroll
                for (int j = 0; j < 8; j++) {
                    #pragma unroll
                    for (int c = 0; c < 2; c++) {
                        const int ki = k0 + j * 8 + 2 * (lane & 3) + c;
                        float v = acc_s[j][half_ * 2 + c];
                        v = (ki <= qi && ki > qi - WIN) ? v * SCALE_F : -1e30f;
                        acc_s[j][half_ * 2 + c] = v;
                        rm = fmaxf(rm, v);
                    }
                }
            } else {
                #pragma unroll
                for (int j = 0; j < 8; j++) {
                    #pragma unroll
                    for (int c = 0; c < 2; c++) {
                        float v = acc_s[j][half_ * 2 + c] * SCALE_F;
                        acc_s[j][half_ * 2 + c] = v;
                        rm = fmaxf(rm, v);
                    }
                }
            }
            rm = fmaxf(rm, __shfl_xor_sync(0xffffffffu, rm, 1));
            rm = fmaxf(rm, __shfl_xor_sync(0xffffffffu, rm, 2));
            const float nm = fmaxf(m[half_], rm);
            const float sc = __expf(m[half_] - nm);
            float rs = 0.0f;
            #pragma unroll
            for (int j = 0; j < 8; j++) {
                #pragma unroll
                for (int c = 0; c < 2; c++) {
                    float v = acc_s[j][half_ * 2 + c];
                    float p = (v > -1e29f) ? __expf(v - nm) : 0.0f;
                    acc_s[j][half_ * 2 + c] = p;
                    rs += p;
                }
            }
            rs += __shfl_xor_sync(0xffffffffu, rs, 1);
            rs += __shfl_xor_sync(0xffffffffu, rs, 2);
            lsum[half_] = lsum[half_] * sc + rs;
            m[half_] = nm;
            #pragma unroll
            for (int n = 0; n < 16; n++) {
                acc_o[n][half_ * 2]     *= sc;
                acc_o[n][half_ * 2 + 1] *= sc;
            }
        }

        // ---- repack P into A fragments (single fp16) ----
        uint32_t aPh[4][4];
        #pragma unroll
        for (int kk = 0; kk < 4; kk++) {
            #pragma unroll
            for (int t = 0; t < 4; t++) {
                const int j = 2 * kk + (t >> 1);
                const int c0 = (t & 1) * 2;
                aPh[kk][t] = pack_h2(acc_s[j][c0], acc_s[j][c0 + 1]);
            }
        }

        // ---- O += P V (2 passes: Ph*Vh + Ph*Vl) ----
        #pragma unroll
        for (int kk = 0; kk < 4; kk++) {
            const int vrow = kk * 16 + (lane & 15);
            const int vcol = (lane >> 4) << 3;
            #pragma unroll
            for (int np = 0; np < 8; np++) {
                uint32_t bh4[4], bl4[4];
                ldmatrix_x4_trans(bh4, smem_u32(Vh + vrow * AST + np * 16 + vcol));
                mma_16816(acc_o[2 * np],     aPh[kk], bh4);
                mma_16816(acc_o[2 * np + 1], aPh[kk], bh4 + 2);
                ldmatrix_x4_trans(bl4, smem_u32(Vl + vrow * AST + np * 16 + vcol));
                mma_16816(acc_o[2 * np],     aPh[kk], bl4);
                mma_16816(acc_o[2 * np + 1], aPh[kk], bl4 + 2);
            }
        }
        __syncthreads();
    }

    // ---- sink fold + write split-fp16 output ----
    const float snk = sinks[h];
    #pragma unroll
    for (int half_ = 0; half_ < 2; half_++) {
        const float M = fmaxf(m[half_], snk);
        const float denom = lsum[half_] * __expf(m[half_] - M) + __expf(snk - M);
        const float ns = __expf(m[half_] - M) / denom;
        const int row = q0 + wq * 16 + r0 + half_ * 8;
        #pragma unroll
        for (int n = 0; n < 16; n++) {
            const float v0 = acc_o[n][half_ * 2] * ns;
            const float v1 = acc_o[n][half_ * 2 + 1] * ns;
            __half2 hp = __floats2half2_rn(v0, v1);
            __half2 lp = __floats2half2_rn(v0 - __half2float(__low2half(hp)),
                                           v1 - __half2float(__high2half(hp)));
            const size_t off = (size_t)row * DM + h * HD + n * 8 + 2 * (lane & 3);
            *(__half2*)(g_ah + off) = hp;
            *(__half2*)(g_al + off) = lp;
        }
    }
}

// ---------------------------------------------------------------------------
// Launch. attn_tc at my-launch idx 3 gets ncu-profiled.
// ---------------------------------------------------------------------------
extern "C" void kernel_launch(void* const* d_in, const int* in_sizes, int n_in,
                              void* d_out, int out_size) {
    const float* x     = (const float*)d_in[0];
    const float* w_q   = (const float*)d_in[1];
    const float* w_k   = (const float*)d_in[2];
    const float* w_v   = (const float*)d_in[3];
    const float* w_out = (const float*)d_in[4];
    const float* qnw   = (const float*)d_in[5];
    const float* knw   = (const float*)d_in[6];
    const float* sinks = (const float*)d_in[7];
    float* out = (float*)d_out;

    cudaFuncSetAttribute(qkv_gemm, cudaFuncAttributeMaxDynamicSharedMemorySize, GEMM_SMEM);
    cudaFuncSetAttribute(out_gemm, cudaFuncAttributeMaxDynamicSharedMemorySize, GEMM_SMEM);
    cudaFuncSetAttribute(attn_tc,  cudaFuncAttributeMaxDynamicSharedMemorySize, ATTN_SMEM);

    // 0: weight splits (hi only)
    split_w_kernel<<<10240, 256>>>(w_q, w_k, w_v, w_out);
    // 1: x split + rope tables
    prep_x_kernel<<<4608, 256>>>(x);
    // 2: fused Q/K/V projection + clip + RMSNorm + RoPE + split epilogues
    qkv_gemm<<<dim3(24, 16), 256, GEMM_SMEM>>>(qnw, knw);
    // 3: windowed flash attention + sink  (profiled slot)
    attn_tc<<<dim3(8, 32), 256, ATTN_SMEM>>>(sinks);
    // 4: output projection
    out_gemm<<<dim3(16, 16), 256, GEMM_SMEM>>>(out);
}

// round 16
// speedup vs baseline: 1.3560x; 1.1810x over previous
#include <cuda_runtime.h>
#include <cuda_fp16.h>
#include <math.h>
#include <stdint.h>

// Problem constants
constexpr int SEQ  = 2048;
constexpr int DM   = 2048;
constexpr int NH   = 16;
constexpr int NKV  = 4;
constexpr int HD   = 128;
constexpr int WIN  = 1024;
constexpr int KVD  = NKV * HD;   // 512
constexpr float CLIPV = 8.0f;
constexpr float SCALE_F = 0.08838834764831845f; // 1/sqrt(128)
constexpr float C2 = 0.12751740f;   // SCALE_F * log2(e)
// Fixed softmax offset. Any constant cancels in p/(sum p + sink); choose it so
// P lands in fp16 normal range: M2 = 12*log2(e) - 14  (R14 used 17.31 -> P
// subnormal in fp16 -> 1.3e-3 rel err). p_max = 2^(16.32-3.31) = 2^13 < 65504.
constexpr float M2 = 3.31234049f;
constexpr float LOG2E = 1.44269504f;

// ---------------------------------------------------------------------------
// Static scratch (no allocations allowed)
// ---------------------------------------------------------------------------
__device__ __half g_xh[SEQ * DM],  g_xl[SEQ * DM];
__device__ __half g_wqh[DM * DM];
__device__ __half g_wkh[KVD * DM];
__device__ __half g_wvh[KVD * DM];
__device__ __half g_woh[DM * DM];
__device__ __half g_ah[SEQ * DM],  g_al[SEQ * DM];      // attn out hi/lo
__device__ __half g_qnh[SEQ * DM], g_qnl[SEQ * DM];     // q normed/roped hi/lo
__device__ __half g_knh[SEQ * KVD], g_knl[SEQ * KVD];   // k normed/roped hi/lo
__device__ __half g_vnh[SEQ * KVD], g_vnl[SEQ * KVD];   // v hi/lo
__device__ float g_cos[SEQ * 64], g_sin[SEQ * 64];      // rope tables

// ---------------------------------------------------------------------------
// PTX helpers
// ---------------------------------------------------------------------------
__device__ __forceinline__ uint32_t smem_u32(const void* p) {
    uint32_t a;
    asm("{ .reg .u64 t; cvta.to.shared.u64 t, %1; cvt.u32.u64 %0, t; }"
        : "=r"(a) : "l"(p));
    return a;
}

__device__ __forceinline__ void cp_async16(uint32_t sp, const void* gp) {
    asm volatile("cp.async.cg.shared.global [%0], [%1], 16;"
                 :: "r"(sp), "l"(gp) : "memory");
}
__device__ __forceinline__ void cp_commit() {
    asm volatile("cp.async.commit_group;" ::: "memory");
}
template <int N>
__device__ __forceinline__ void cp_wait() {
    asm volatile("cp.async.wait_group %0;" :: "n"(N) : "memory");
}

__device__ __forceinline__ void ldmatrix_x4(uint32_t* r, uint32_t addr) {
    asm volatile("ldmatrix.sync.aligned.m8n8.x4.shared.b16 {%0,%1,%2,%3}, [%4];"
                 : "=r"(r[0]), "=r"(r[1]), "=r"(r[2]), "=r"(r[3]) : "r"(addr));
}
__device__ __forceinline__ void ldmatrix_x4_trans(uint32_t* r, uint32_t addr) {
    asm volatile("ldmatrix.sync.aligned.m8n8.x4.trans.shared.b16 {%0,%1,%2,%3}, [%4];"
                 : "=r"(r[0]), "=r"(r[1]), "=r"(r[2]), "=r"(r[3]) : "r"(addr));
}

__device__ __forceinline__ void mma_16816(float* c, const uint32_t* a, const uint32_t* b) {
    asm volatile(
        "mma.sync.aligned.m16n8k16.row.col.f32.f16.f16.f32 "
        "{%0,%1,%2,%3}, {%4,%5,%6,%7}, {%8,%9}, {%0,%1,%2,%3};"
        : "+f"(c[0]), "+f"(c[1]), "+f"(c[2]), "+f"(c[3])
        : "r"(a[0]), "r"(a[1]), "r"(a[2]), "r"(a[3]), "r"(b[0]), "r"(b[1]));
}

__device__ __forceinline__ uint32_t pack_h2(float a, float b) {
    __half2 h = __floats2half2_rn(a, b);
    return *(uint32_t*)&h;
}

__device__ __forceinline__ float ex2(float x) {
    float y;
    asm("ex2.approx.f32 %0, %1;" : "=f"(y) : "f"(x));
    return y;
}

// ---------------------------------------------------------------------------
// Splits fp32 -> fp16 (hi[, lo])
// ---------------------------------------------------------------------------
__device__ __forceinline__ void split_hl(const float* __restrict__ x,
                                         __half* __restrict__ hi,
                                         __half* __restrict__ lo, int i) {
    float4 v = ((const float4*)x)[i];
    __half h0 = __float2half_rn(v.x), h1 = __float2half_rn(v.y);
    __half h2 = __float2half_rn(v.z), h3 = __float2half_rn(v.w);
    __half l0 = __float2half_rn(v.x - __half2float(h0));
    __half l1 = __float2half_rn(v.y - __half2float(h1));
    __half l2 = __float2half_rn(v.z - __half2float(h2));
    __half l3 = __float2half_rn(v.w - __half2float(h3));
    __half2 hp0 = __halves2half2(h0, h1), hp1 = __halves2half2(h2, h3);
    __half2 lp0 = __halves2half2(l0, l1), lp1 = __halves2half2(l2, l3);
    uint2 hv, lv;
    hv.x = *(uint32_t*)&hp0; hv.y = *(uint32_t*)&hp1;
    lv.x = *(uint32_t*)&lp0; lv.y = *(uint32_t*)&lp1;
    ((uint2*)hi)[i] = hv;
    ((uint2*)lo)[i] = lv;
}

__device__ __forceinline__ void split_h(const float* __restrict__ x,
                                        __half* __restrict__ hi, int i) {
    float4 v = ((const float4*)x)[i];
    __half2 hp0 = __floats2half2_rn(v.x, v.y);
    __half2 hp1 = __floats2half2_rn(v.z, v.w);
    uint2 hv;
    hv.x = *(uint32_t*)&hp0; hv.y = *(uint32_t*)&hp1;
    ((uint2*)hi)[i] = hv;
}

// Weight splits (hi only). grid = 10240 blocks.
__global__ void split_w_kernel(const float* __restrict__ wq, const float* __restrict__ wk,
                               const float* __restrict__ wv, const float* __restrict__ wo) {
    int b = blockIdx.x;
    if (b < 4096) {
        split_h(wq, g_wqh, b * 256 + threadIdx.x);
    } else if (b < 5120) {
        split_h(wk, g_wkh, (b - 4096) * 256 + threadIdx.x);
    } else if (b < 6144) {
        split_h(wv, g_wvh, (b - 5120) * 256 + threadIdx.x);
    } else {
        split_h(wo, g_woh, (b - 6144) * 256 + threadIdx.x);
    }
}

// x split (hi/lo) + rope tables. grid = 4608 blocks.
__global__ void prep_x_kernel(const float* __restrict__ x) {
    int b = blockIdx.x;
    if (b < 4096) {
        split_hl(x, g_xh, g_xl, b * 256 + threadIdx.x);
    } else {
        int idx = (b - 4096) * 256 + threadIdx.x;
        int s = idx >> 6, d = idx & 63;
        float inv = powf(500000.0f, -(float)d * (1.0f / 64.0f));
        float sn, cs;
        sincosf((float)s * inv, &sn, &cs);
        g_cos[s * 64 + d] = cs;
        g_sin[s * 64 + d] = sn;
    }
}

// ---------------------------------------------------------------------------
// GEMM core (fp16 2-pass): 128x128 tile, 256 thr, BK=32,
// 3-stage cp.async pipeline. Per stage: Ah | Al | Bh (3 tiles).
// ---------------------------------------------------------------------------
constexpr int LDSROW = 40;
constexpr int TILE_B = 128 * LDSROW * 2;    // 10240 B
constexpr int CHUNK_B = 3 * TILE_B;         // 30720 B per stage
constexpr int GEMM_SMEM = 3 * CHUNK_B;      // 92160 B (epi needs 69.7KB, fits)

__device__ __forceinline__ void gemm_core(
    const __half* __restrict__ Ah, const __half* __restrict__ Al,
    const __half* __restrict__ Bh,
    int K, float acc[4][4][4], char* dsm) {
    const uint32_t sm0 = smem_u32(dsm);
    const int tid = threadIdx.x;
    const int wid = tid >> 5;
    const int lane = tid & 31;
    const int warp_m = wid & 1;
    const int warp_n = wid >> 1;
    const int NC = K >> 5;

    #pragma unroll
    for (int i = 0; i < 4; i++)
        #pragma unroll
        for (int j = 0; j < 4; j++)
            #pragma unroll
            for (int t = 0; t < 4; t++) acc[i][j][t] = 0.0f;

    auto load_chunk = [&](int c, int s) {
        const int k0 = c << 5;
        const uint32_t b = sm0 + s * CHUNK_B;
        #pragma unroll
        for (int t = 0; t < 2; t++) {
            int idx = tid + t * 256;
            int r = idx >> 2, g = idx & 3;
            uint32_t off = (uint32_t)(r * LDSROW + g * 8) * 2;
            const size_t ga = (size_t)r * K + k0 + g * 8;
            cp_async16(b + off, Ah + ga);
            cp_async16(b + TILE_B + off, Al + ga);
            cp_async16(b + 2 * TILE_B + off, Bh + ga);
        }
    };

    load_chunk(0, 0);
    cp_commit();
    load_chunk(1, 1);
    cp_commit();

    int sld = 2;
    for (int c = 0; c < NC; c++) {
        if (c + 2 < NC) {
            load_chunk(c + 2, sld);
            if (++sld == 3) sld = 0;
            cp_commit();
            cp_wait<2>();
        } else if (c + 1 < NC) {
            cp_wait<1>();
        } else {
            cp_wait<0>();
        }
        __syncthreads();

        const uint32_t b = sm0 + (c % 3) * CHUNK_B;
        #pragma unroll
        for (int ks = 0; ks < 2; ks++) {
            const int kc = ks * 16;
            uint32_t ah4[4][4], bh[4][2];
            #pragma unroll
            for (int im = 0; im < 4; im++) {
                int row = warp_m * 64 + im * 16 + (lane & 15);
                int col = kc + ((lane >> 4) << 3);
                ldmatrix_x4(ah4[im], b + (uint32_t)(row * LDSROW + col) * 2);
            }
            #pragma unroll
            for (int ib = 0; ib < 2; ib++) {
                int n = warp_n * 32 + ib * 16 + (lane & 7) + ((lane >> 4) << 3);
                int col = kc + (lane & 8);
                uint32_t r4[4];
                ldmatrix_x4(r4, b + 2 * TILE_B + (uint32_t)(n * LDSROW + col) * 2);
                bh[ib * 2][0] = r4[0]; bh[ib * 2][1] = r4[1];
                bh[ib * 2 + 1][0] = r4[2]; bh[ib * 2 + 1][1] = r4[3];
            }
            #pragma unroll
            for (int im = 0; im < 4; im++)
                #pragma unroll
                for (int in = 0; in < 4; in++)
                    mma_16816(acc[im][in], ah4[im], bh[in]);
            #pragma unroll
            for (int im = 0; im < 4; im++) {
                int row = warp_m * 64 + im * 16 + (lane & 15);
                int col = kc + ((lane >> 4) << 3);
                ldmatrix_x4(ah4[im], b + TILE_B + (uint32_t)(row * LDSROW + col) * 2);
            }
            #pragma unroll
            for (int im = 0; im < 4; im++)
                #pragma unroll
                for (int in = 0; in < 4; in++)
                    mma_16816(acc[im][in], ah4[im], bh[in]);
        }
        __syncthreads();
    }
}

// Epilogue: clip + RMSNorm + RoPE + split-fp16 write (one head per col-block).
__device__ __forceinline__ void epi_norm_rope(
    float acc[4][4][4], char* dsm, int row0, int col0, int LD,
    const float* __restrict__ w,
    __half* __restrict__ dh, __half* __restrict__ dl) {
    const int tid = threadIdx.x;
    const int wid = tid >> 5;
    const int lane = tid & 31;
    const int warp_m = wid & 1;
    const int warp_n = wid >> 1;
    float* xs = (float*)dsm;                 // [128][132]
    float* rs = xs + 128 * 132;              // [128][4]

    #pragma unroll
    for (int im = 0; im < 4; im++) {
        #pragma unroll
        for (int half_ = 0; half_ < 2; half_++) {
            const int rl = warp_m * 64 + im * 16 + (lane >> 2) + half_ * 8;
            float ss = 0.0f;
            #pragma unroll
            for (int in = 0; in < 4; in++) {
                #pragma unroll
                for (int c = 0; c < 2; c++) {
                    float v = acc[im][in][half_ * 2 + c];
                    v = fminf(fmaxf(v, -CLIPV), CLIPV);
                    acc[im][in][half_ * 2 + c] = v;
                    xs[rl * 132 + warp_n * 32 + in * 8 + 2 * (lane & 3) + c] = v;
                    ss += v * v;
                }
            }
            ss += __shfl_xor_sync(0xffffffffu, ss, 1);
            ss += __shfl_xor_sync(0xffffffffu, ss, 2);
            if ((lane & 3) == 0) rs[rl * 4 + warp_n] = ss;
        }
    }
    __syncthreads();

    #pragma unroll
    for (int im = 0; im < 4; im++) {
        #pragma unroll
        for (int half_ = 0; half_ < 2; half_++) {
            const int rl = warp_m * 64 + im * 16 + (lane >> 2) + half_ * 8;
            const int pos = row0 + rl;
            const float sum = rs[rl * 4] + rs[rl * 4 + 1] + rs[rl * 4 + 2] + rs[rl * 4 + 3];
            const float rsig = rsqrtf(sum * (1.0f / HD) + 1e-6f);
            #pragma unroll
            for (int in = 0; in < 4; in++) {
                const int col = warp_n * 32 + in * 8 + 2 * (lane & 3);
                float o[2];
                #pragma unroll
                for (int c = 0; c < 2; c++) {
                    const int cc = col + c;
                    const float xn = acc[im][in][half_ * 2 + c] * rsig * w[cc];
                    const float xp = xs[rl * 132 + (cc ^ 64)] * rsig * w[cc ^ 64];
                    const float cs = g_cos[pos * 64 + (cc & 63)];
                    const float sn = g_sin[pos * 64 + (cc & 63)];
                    o[c] = xn * cs + ((cc < 64) ? -xp : xp) * sn;
                }
                __half2 hp = __floats2half2_rn(o[0], o[1]);
                __half2 lp = __floats2half2_rn(o[0] - __half2float(__low2half(hp)),
                                               o[1] - __half2float(__high2half(hp)));
                const size_t off = (size_t)pos * LD + col0 + col;
                *(__half2*)(dh + off) = hp;
                *(__half2*)(dl + off) = lp;
            }
        }
    }
}

// Epilogue: clip + split-fp16 write (V path).
__device__ __forceinline__ void epi_split(
    float acc[4][4][4], int row0, int col0, int LD,
    __half* __restrict__ dh, __half* __restrict__ dl) {
    const int tid = threadIdx.x;
    const int wid = tid >> 5;
    const int lane = tid & 31;
    const int warp_m = wid & 1;
    const int warp_n = wid >> 1;
    #pragma unroll
    for (int im = 0; im < 4; im++) {
        #pragma unroll
        for (int half_ = 0; half_ < 2; half_++) {
            const int row = row0 + warp_m * 64 + im * 16 + (lane >> 2) + half_ * 8;
            #pragma unroll
            for (int in = 0; in < 4; in++) {
                const int col = warp_n * 32 + in * 8 + 2 * (lane & 3);
                float o[2];
                #pragma unroll
                for (int c = 0; c < 2; c++)
                    o[c] = fminf(fmaxf(acc[im][in][half_ * 2 + c], -CLIPV), CLIPV);
                __half2 hp = __floats2half2_rn(o[0], o[1]);
                __half2 lp = __floats2half2_rn(o[0] - __half2float(__low2half(hp)),
                                               o[1] - __half2float(__high2half(hp)));
                const size_t off = (size_t)row * LD + col0 + col;
                *(__half2*)(dh + off) = hp;
                *(__half2*)(dl + off) = lp;
            }
        }
    }
}

// Fused Q/K/V projection + norm/rope/split epilogues. grid (24, 16).
__global__ __launch_bounds__(256, 2) void qkv_gemm(const float* __restrict__ qnw,
                                                   const float* __restrict__ knw) {
    extern __shared__ char dsm[];
    const int cx = blockIdx.x;
    const int row0 = blockIdx.y << 7;
    float acc[4][4][4];
    if (cx < 16) {
        const size_t bo = (size_t)(cx << 7) * DM;
        gemm_core(g_xh + (size_t)row0 * DM, g_xl + (size_t)row0 * DM,
                  g_wqh + bo, DM, acc, dsm);
        epi_norm_rope(acc, dsm, row0, cx << 7, DM, qnw, g_qnh, g_qnl);
    } else if (cx < 20) {
        const size_t bo = (size_t)((cx - 16) << 7) * DM;
        gemm_core(g_xh + (size_t)row0 * DM, g_xl + (size_t)row0 * DM,
                  g_wkh + bo, DM, acc, dsm);
        epi_norm_rope(acc, dsm, row0, (cx - 16) << 7, KVD, knw, g_knh, g_knl);
    } else {
        const size_t bo = (size_t)((cx - 20) << 7) * DM;
        gemm_core(g_xh + (size_t)row0 * DM, g_xl + (size_t)row0 * DM,
                  g_wvh + bo, DM, acc, dsm);
        epi_split(acc, row0, (cx - 20) << 7, KVD, g_vnh, g_vnl);
    }
}

// Output projection: plain fp32 epilogue.
__global__ __launch_bounds__(256, 2) void out_gemm(float* __restrict__ out) {
    extern __shared__ char dsm[];
    const int row0 = blockIdx.y << 7;
    const int col0 = blockIdx.x << 7;
    float acc[4][4][4];
    gemm_core(g_ah + (size_t)row0 * DM, g_al + (size_t)row0 * DM,
              g_woh + (size_t)col0 * DM, DM, acc, dsm);
    const int tid = threadIdx.x;
    const int wid = tid >> 5;
    const int lane = tid & 31;
    const int warp_m = wid & 1;
    const int warp_n = wid >> 1;
    #pragma unroll
    for (int im = 0; im < 4; im++) {
        const int row = row0 + warp_m * 64 + im * 16 + (lane >> 2);
        #pragma unroll
        for (int in = 0; in < 4; in++) {
            const int col = col0 + warp_n * 32 + in * 8 + 2 * (lane & 3);
            *(float2*)(out + (size_t)row * DM + col) =
                make_float2(acc[im][in][0], acc[im][in][1]);
            *(float2*)(out + (size_t)(row + 8) * DM + col) =
                make_float2(acc[im][in][2], acc[im][in][3]);
        }
    }
}

// ---------------------------------------------------------------------------
// Tensor-core flash attention v3: 1 head per 128-thread CTA, Q in registers,
// K double-buffered, V single-buffered (FIFO wait_group pipeline),
// fixed-offset softmax (offset chosen so P is fp16-normal; exact math).
// grid = (16 heads, 32 qtiles rev). 2 CTAs/SM. AST=136 (272B, 16-aligned).
// ---------------------------------------------------------------------------
constexpr int AST = 136;                    // smem row stride (halves)
constexpr int T2E = 64 * AST;               // 8704 halves per 64x128 tile
constexpr int ATTN_SMEM = 6 * T2E * 2;      // 104448 B

__global__ __launch_bounds__(128, 2) void attn_tc(const float* __restrict__ sinks) {
    extern __shared__ __half smb[];
    // tiles: [0]=Kh0 [1]=Kl0 [2]=Kh1 [3]=Kl1 [4]=Vh [5]=Vl  (Q staged in 0,1)
    const int h = blockIdx.x;
    const int qt = 31 - (int)blockIdx.y;     // big q-tiles first
    const int q0 = qt << 6;
    const int kvh = h >> 2;
    const int tid = threadIdx.x;
    const int wid = tid >> 5;                // warp = 16 q rows
    const int lane = tid & 31;
    const int r0 = lane >> 2;

    // ---- stage Q (hi/lo) into K buffer 0, move to registers ----
    for (int idx = tid; idx < 1024; idx += 128) {
        int r = idx >> 4, c = idx & 15;
        const size_t go = (size_t)(q0 + r) * DM + h * HD + c * 8;
        cp_async16(smem_u32(smb + r * AST + c * 8), g_qnh + go);
        cp_async16(smem_u32(smb + T2E + r * AST + c * 8), g_qnl + go);
    }
    cp_commit();
    cp_wait<0>();
    __syncthreads();

    uint32_t aQh[8][4], aQl[8][4];
    {
        const int qrow = wid * 16 + (lane & 15);
        #pragma unroll
        for (int ks = 0; ks < 8; ks++) {
            const int qcol = ks * 16 + ((lane >> 4) << 3);
            ldmatrix_x4(aQh[ks], smem_u32(smb + qrow * AST + qcol));
            ldmatrix_x4(aQl[ks], smem_u32(smb + T2E + qrow * AST + qcol));
        }
    }
    __syncthreads();   // everyone done reading Q staging before K overwrites

    auto load_K = [&](int kt, int b) {
        const int k0 = kt << 6;
        __half* Kh = smb + 2 * b * T2E;
        __half* Kl = Kh + T2E;
        for (int idx = tid; idx < 1024; idx += 128) {
            int r = idx >> 4, c = idx & 15;
            const size_t go = (size_t)(k0 + r) * KVD + kvh * HD + c * 8;
            cp_async16(smem_u32(Kh + r * AST + c * 8), g_knh + go);
            cp_async16(smem_u32(Kl + r * AST + c * 8), g_knl + go);
        }
    };
    auto load_V = [&](int kt) {
        const int k0 = kt << 6;
        __half* Vh = smb + 4 * T2E;
        __half* Vl = Vh + T2E;
        for (int idx = tid; idx < 1024; idx += 128) {
            int r = idx >> 4, c = idx & 15;
            const size_t go = (size_t)(k0 + r) * KVD + kvh * HD + c * 8;
            cp_async16(smem_u32(Vh + r * AST + c * 8), g_vnh + go);
            cp_async16(smem_u32(Vl + r * AST + c * 8), g_vnl + go);
        }
    };

    int lo = q0 - WIN + 1;
    if (lo < 0) lo = 0;
    const int kt_lo = lo >> 6;
    load_K(kt_lo, 0);
    cp_commit();
    load_V(kt_lo);
    cp_commit();

    float lsum[2] = {0.0f, 0.0f};
    float acc_o[16][4];
    #pragma unroll
    for (int n = 0; n < 16; n++)
        #pragma unroll
        for (int t = 0; t < 4; t++) acc_o[n][t] = 0.0f;

    for (int kt = kt_lo; kt <= qt; kt++) {
        const int b = (kt - kt_lo) & 1;
        const int k0 = kt << 6;
        const bool need_mask = (kt == qt) || (k0 < lo);
        if (kt < qt) {
            load_K(kt + 1, b ^ 1);
            cp_commit();
            cp_wait<1>();       // FIFO: forces K(kt), V(kt) complete
        } else {
            cp_wait<0>();
        }
        __syncthreads();

        __half* Kh = smb + 2 * b * T2E;
        __half* Kl = Kh + T2E;
        __half* Vh = smb + 4 * T2E;
        __half* Vl = Vh + T2E;

        // ---- S = Q K^T (3 split passes, Q from registers) ----
        float acc_s[8][4];
        #pragma unroll
        for (int j = 0; j < 8; j++)
            #pragma unroll
            for (int t = 0; t < 4; t++) acc_s[j][t] = 0.0f;

        #pragma unroll
        for (int ks = 0; ks < 8; ks++) {
            #pragma unroll
            for (int np = 0; np < 4; np++) {
                const int n = np * 16 + (lane & 7) + ((lane >> 4) << 3);
                const int col = ks * 16 + (lane & 8);
                uint32_t bh4[4], bl4[4];
                ldmatrix_x4(bh4, smem_u32(Kh + n * AST + col));
                ldmatrix_x4(bl4, smem_u32(Kl + n * AST + col));
                mma_16816(acc_s[2 * np],     aQh[ks], bh4);
                mma_16816(acc_s[2 * np],     aQl[ks], bh4);
                mma_16816(acc_s[2 * np],     aQh[ks], bl4);
                mma_16816(acc_s[2 * np + 1], aQh[ks], bh4 + 2);
                mma_16816(acc_s[2 * np + 1], aQl[ks], bh4 + 2);
                mma_16816(acc_s[2 * np + 1], aQh[ks], bl4 + 2);
            }
        }

        // ---- fixed-offset softmax: p = 2^(s*C2 - M2), masked -> 0 ----
        #pragma unroll
        for (int half_ = 0; half_ < 2; half_++) {
            const int qi = q0 + wid * 16 + r0 + half_ * 8;
            float rs = 0.0f;
            if (need_mask) {
                #pragma unroll
                for (int j = 0; j < 8; j++) {
                    #pragma unroll
                    for (int c = 0; c < 2; c++) {
                        const int ki = k0 + j * 8 + 2 * (lane & 3) + c;
                        const bool ok = (ki <= qi) && (ki > qi - WIN);
                        float p = ok ? ex2(fmaf(acc_s[j][half_ * 2 + c], C2, -M2)) : 0.0f;
                        acc_s[j][half_ * 2 + c] = p;
                        rs += p;
                    }
                }
            } else {
                #pragma unroll
                for (int j = 0; j < 8; j++) {
                    #pragma unroll
                    for (int c = 0; c < 2; c++) {
                        float p = ex2(fmaf(acc_s[j][half_ * 2 + c], C2, -M2));
                        acc_s[j][half_ * 2 + c] = p;
                        rs += p;
                    }
                }
            }
            rs += __shfl_xor_sync(0xffffffffu, rs, 1);
            rs += __shfl_xor_sync(0xffffffffu, rs, 2);
            lsum[half_] += rs;
        }

        // ---- repack P into A fragments (single fp16) ----
        uint32_t aP[4][4];
        #pragma unroll
        for (int kk = 0; kk < 4; kk++) {
            #pragma unroll
            for (int t = 0; t < 4; t++) {
                const int j = 2 * kk + (t >> 1);
                const int c0 = (t & 1) * 2;
                aP[kk][t] = pack_h2(acc_s[j][c0], acc_s[j][c0 + 1]);
            }
        }

        // ---- O += P V (2 passes: P*Vh + P*Vl) ----
        #pragma unroll
        for (int kk = 0; kk < 4; kk++) {
            const int vrow = kk * 16 + (lane & 15);
            const int vcol = (lane >> 4) << 3;
            #pragma unroll
            for (int np = 0; np < 8; np++) {
                uint32_t bh4[4], bl4[4];
                ldmatrix_x4_trans(bh4, smem_u32(Vh + vrow * AST + np * 16 + vcol));
                mma_16816(acc_o[2 * np],     aP[kk], bh4);
                mma_16816(acc_o[2 * np + 1], aP[kk], bh4 + 2);
                ldmatrix_x4_trans(bl4, smem_u32(Vl + vrow * AST + np * 16 + vcol));
                mma_16816(acc_o[2 * np],     aP[kk], bl4);
                mma_16816(acc_o[2 * np + 1], aP[kk], bl4 + 2);
            }
        }
        __syncthreads();   // all warps done with V before next V load
        if (kt < qt) {
            load_V(kt + 1);
            cp_commit();
        }
    }

    // ---- sink fold + write split-fp16 output ----
    const float snk = sinks[h];
    const float sinkterm = ex2(fmaf(snk, LOG2E, -M2));
    #pragma unroll
    for (int half_ = 0; half_ < 2; half_++) {
        const float ns = 1.0f / (lsum[half_] + sinkterm);
        const int row = q0 + wid * 16 + r0 + half_ * 8;
        #pragma unroll
        for (int n = 0; n < 16; n++) {
            const float v0 = acc_o[n][half_ * 2] * ns;
            const float v1 = acc_o[n][half_ * 2 + 1] * ns;
            __half2 hp = __floats2half2_rn(v0, v1);
            __half2 lp = __floats2half2_rn(v0 - __half2float(__low2half(hp)),
                                           v1 - __half2float(__high2half(hp)));
            const size_t off = (size_t)row * DM + h * HD + n * 8 + 2 * (lane & 3);
            *(__half2*)(g_ah + off) = hp;
            *(__half2*)(g_al + off) = lp;
        }
    }
}

// ---------------------------------------------------------------------------
// Launch. attn_tc at my-launch idx 3 gets ncu-profiled.
// ---------------------------------------------------------------------------
extern "C" void kernel_launch(void* const* d_in, const int* in_sizes, int n_in,
                              void* d_out, int out_size) {
    const float* x     = (const float*)d_in[0];
    const float* w_q   = (const float*)d_in[1];
    const float* w_k   = (const float*)d_in[2];
    const float* w_v   = (const float*)d_in[3];
    const float* w_out = (const float*)d_in[4];
    const float* qnw   = (const float*)d_in[5];
    const float* knw   = (const float*)d_in[6];
    const float* sinks = (const float*)d_in[7];
    float* out = (float*)d_out;

    cudaFuncSetAttribute(qkv_gemm, cudaFuncAttributeMaxDynamicSharedMemorySize, GEMM_SMEM);
    cudaFuncSetAttribute(out_gemm, cudaFuncAttributeMaxDynamicSharedMemorySize, GEMM_SMEM);
    cudaFuncSetAttribute(attn_tc,  cudaFuncAttributeMaxDynamicSharedMemorySize, ATTN_SMEM);

    // 0: weight splits (hi only)
    split_w_kernel<<<10240, 256>>>(w_q, w_k, w_v, w_out);
    // 1: x split + rope tables
    prep_x_kernel<<<4608, 256>>>(x);
    // 2: fused Q/K/V projection + clip + RMSNorm + RoPE + split epilogues
    qkv_gemm<<<dim3(24, 16), 256, GEMM_SMEM>>>(qnw, knw);
    // 3: windowed flash attention + sink  (profiled slot)
    attn_tc<<<dim3(NH, 32), 128, ATTN_SMEM>>>(sinks);
    // 4: output projection
    out_gemm<<<dim3(16, 16), 256, GEMM_SMEM>>>(out);
}

// round 17
// speedup vs baseline: 1.4216x; 1.0484x over previous
#include <cuda_runtime.h>
#include <cuda_fp16.h>
#include <math.h>
#include <stdint.h>

// Problem constants
constexpr int SEQ  = 2048;
constexpr int DM   = 2048;
constexpr int NH   = 16;
constexpr int NKV  = 4;
constexpr int HD   = 128;
constexpr int WIN  = 1024;
constexpr int KVD  = NKV * HD;   // 512
constexpr float CLIPV = 8.0f;
constexpr float SCALE_F = 0.08838834764831845f; // 1/sqrt(128)
constexpr float C2 = 0.12751740f;   // SCALE_F * log2(e)
// Fixed softmax offset: chosen so P sits in fp16-normal range (R14 lesson).
constexpr float M2 = 3.31234049f;   // 12*log2(e) - 14
constexpr float LOG2E = 1.44269504f;

// ---------------------------------------------------------------------------
// Static scratch (no allocations allowed)
// ---------------------------------------------------------------------------
__device__ __half g_xh[SEQ * DM],  g_xl[SEQ * DM];
__device__ __half g_wqh[DM * DM];
__device__ __half g_wkh[KVD * DM];
__device__ __half g_wvh[KVD * DM];
__device__ __half g_woh[DM * DM];
__device__ __half g_ah[SEQ * DM],  g_al[SEQ * DM];      // attn out hi/lo
__device__ __half g_qnh[SEQ * DM], g_qnl[SEQ * DM];     // q normed/roped hi/lo
__device__ __half g_knh[SEQ * KVD];                     // k normed/roped (hi only)
__device__ __half g_vnh[SEQ * KVD], g_vnl[SEQ * KVD];   // v hi/lo
__device__ float g_cos[SEQ * 64], g_sin[SEQ * 64];      // rope tables

// ---------------------------------------------------------------------------
// PTX helpers
// ---------------------------------------------------------------------------
__device__ __forceinline__ uint32_t smem_u32(const void* p) {
    uint32_t a;
    asm("{ .reg .u64 t; cvta.to.shared.u64 t, %1; cvt.u32.u64 %0, t; }"
        : "=r"(a) : "l"(p));
    return a;
}

__device__ __forceinline__ void cp_async16(uint32_t sp, const void* gp) {
    asm volatile("cp.async.cg.shared.global [%0], [%1], 16;"
                 :: "r"(sp), "l"(gp) : "memory");
}
__device__ __forceinline__ void cp_commit() {
    asm volatile("cp.async.commit_group;" ::: "memory");
}
template <int N>
__device__ __forceinline__ void cp_wait() {
    asm volatile("cp.async.wait_group %0;" :: "n"(N) : "memory");
}

__device__ __forceinline__ void ldmatrix_x4(uint32_t* r, uint32_t addr) {
    asm volatile("ldmatrix.sync.aligned.m8n8.x4.shared.b16 {%0,%1,%2,%3}, [%4];"
                 : "=r"(r[0]), "=r"(r[1]), "=r"(r[2]), "=r"(r[3]) : "r"(addr));
}
__device__ __forceinline__ void ldmatrix_x4_trans(uint32_t* r, uint32_t addr) {
    asm volatile("ldmatrix.sync.aligned.m8n8.x4.trans.shared.b16 {%0,%1,%2,%3}, [%4];"
                 : "=r"(r[0]), "=r"(r[1]), "=r"(r[2]), "=r"(r[3]) : "r"(addr));
}

__device__ __forceinline__ void mma_16816(float* c, const uint32_t* a, const uint32_t* b) {
    asm volatile(
        "mma.sync.aligned.m16n8k16.row.col.f32.f16.f16.f32 "
        "{%0,%1,%2,%3}, {%4,%5,%6,%7}, {%8,%9}, {%0,%1,%2,%3};"
        : "+f"(c[0]), "+f"(c[1]), "+f"(c[2]), "+f"(c[3])
        : "r"(a[0]), "r"(a[1]), "r"(a[2]), "r"(a[3]), "r"(b[0]), "r"(b[1]));
}

__device__ __forceinline__ uint32_t pack_h2(float a, float b) {
    __half2 h = __floats2half2_rn(a, b);
    return *(uint32_t*)&h;
}

__device__ __forceinline__ float ex2(float x) {
    float y;
    asm("ex2.approx.f32 %0, %1;" : "=f"(y) : "f"(x));
    return y;
}

// ---------------------------------------------------------------------------
// Splits fp32 -> fp16 (hi[, lo])
// ---------------------------------------------------------------------------
__device__ __forceinline__ void split_hl(const float* __restrict__ x,
                                         __half* __restrict__ hi,
                                         __half* __restrict__ lo, int i) {
    float4 v = ((const float4*)x)[i];
    __half h0 = __float2half_rn(v.x), h1 = __float2half_rn(v.y);
    __half h2 = __float2half_rn(v.z), h3 = __float2half_rn(v.w);
    __half l0 = __float2half_rn(v.x - __half2float(h0));
    __half l1 = __float2half_rn(v.y - __half2float(h1));
    __half l2 = __float2half_rn(v.z - __half2float(h2));
    __half l3 = __float2half_rn(v.w - __half2float(h3));
    __half2 hp0 = __halves2half2(h0, h1), hp1 = __halves2half2(h2, h3);
    __half2 lp0 = __halves2half2(l0, l1), lp1 = __halves2half2(l2, l3);
    uint2 hv, lv;
    hv.x = *(uint32_t*)&hp0; hv.y = *(uint32_t*)&hp1;
    lv.x = *(uint32_t*)&lp0; lv.y = *(uint32_t*)&lp1;
    ((uint2*)hi)[i] = hv;
    ((uint2*)lo)[i] = lv;
}

__device__ __forceinline__ void split_h(const float* __restrict__ x,
                                        __half* __restrict__ hi, int i) {
    float4 v = ((const float4*)x)[i];
    __half2 hp0 = __floats2half2_rn(v.x, v.y);
    __half2 hp1 = __floats2half2_rn(v.z, v.w);
    uint2 hv;
    hv.x = *(uint32_t*)&hp0; hv.y = *(uint32_t*)&hp1;
    ((uint2*)hi)[i] = hv;
}

// Weight splits, part 1: wq + wk. grid = 5120 blocks.
__global__ void split_w1_kernel(const float* __restrict__ wq,
                                const float* __restrict__ wk) {
    int b = blockIdx.x;
    if (b < 4096) split_h(wq, g_wqh, b * 256 + threadIdx.x);
    else          split_h(wk, g_wkh, (b - 4096) * 256 + threadIdx.x);
}

// Weight splits, part 2: wv + wo. grid = 5120 blocks.
__global__ void split_w2_kernel(const float* __restrict__ wv,
                                const float* __restrict__ wo) {
    int b = blockIdx.x;
    if (b < 1024) split_h(wv, g_wvh, b * 256 + threadIdx.x);
    else          split_h(wo, g_woh, (b - 1024) * 256 + threadIdx.x);
}

// x split (hi/lo) + rope tables. grid = 4608 blocks.
__global__ void prep_x_kernel(const float* __restrict__ x) {
    int b = blockIdx.x;
    if (b < 4096) {
        split_hl(x, g_xh, g_xl, b * 256 + threadIdx.x);
    } else {
        int idx = (b - 4096) * 256 + threadIdx.x;
        int s = idx >> 6, d = idx & 63;
        float inv = powf(500000.0f, -(float)d * (1.0f / 64.0f));
        float sn, cs;
        sincosf((float)s * inv, &sn, &cs);
        g_cos[s * 64 + d] = cs;
        g_sin[s * 64 + d] = sn;
    }
}

// ---------------------------------------------------------------------------
// GEMM core (fp16 2-pass): 128x128 tile, 256 thr, BK=32,
// 3-stage cp.async pipeline. Per stage: Ah | Al | Bh (3 tiles).
// A-hi, B, A-lo fragments all loaded up front -> 32 back-to-back MMAs.
// ---------------------------------------------------------------------------
constexpr int LDSROW = 40;
constexpr int TILE_B = 128 * LDSROW * 2;    // 10240 B
constexpr int CHUNK_B = 3 * TILE_B;         // 30720 B per stage
constexpr int GEMM_SMEM = 3 * CHUNK_B;      // 92160 B (epi needs 69.7KB, fits)

__device__ __forceinline__ void gemm_core(
    const __half* __restrict__ Ah, const __half* __restrict__ Al,
    const __half* __restrict__ Bh,
    int K, float acc[4][4][4], char* dsm) {
    const uint32_t sm0 = smem_u32(dsm);
    const int tid = threadIdx.x;
    const int wid = tid >> 5;
    const int lane = tid & 31;
    const int warp_m = wid & 1;
    const int warp_n = wid >> 1;
    const int NC = K >> 5;

    #pragma unroll
    for (int i = 0; i < 4; i++)
        #pragma unroll
        for (int j = 0; j < 4; j++)
            #pragma unroll
            for (int t = 0; t < 4; t++) acc[i][j][t] = 0.0f;

    auto load_chunk = [&](int c, int s) {
        const int k0 = c << 5;
        const uint32_t b = sm0 + s * CHUNK_B;
        #pragma unroll
        for (int t = 0; t < 2; t++) {
            int idx = tid + t * 256;
            int r = idx >> 2, g = idx & 3;
            uint32_t off = (uint32_t)(r * LDSROW + g * 8) * 2;
            const size_t ga = (size_t)r * K + k0 + g * 8;
            cp_async16(b + off, Ah + ga);
            cp_async16(b + TILE_B + off, Al + ga);
            cp_async16(b + 2 * TILE_B + off, Bh + ga);
        }
    };

    load_chunk(0, 0);
    cp_commit();
    load_chunk(1, 1);
    cp_commit();

    int sld = 2;
    for (int c = 0; c < NC; c++) {
        if (c + 2 < NC) {
            load_chunk(c + 2, sld);
            if (++sld == 3) sld = 0;
            cp_commit();
            cp_wait<2>();
        } else if (c + 1 < NC) {
            cp_wait<1>();
        } else {
            cp_wait<0>();
        }
        __syncthreads();

        const uint32_t b = sm0 + (c % 3) * CHUNK_B;
        #pragma unroll
        for (int ks = 0; ks < 2; ks++) {
            const int kc = ks * 16;
            uint32_t ah4[4][4], al4[4][4], bh[4][2];
            #pragma unroll
            for (int im = 0; im < 4; im++) {
                int row = warp_m * 64 + im * 16 + (lane & 15);
                int col = kc + ((lane >> 4) << 3);
                ldmatrix_x4(ah4[im], b + (uint32_t)(row * LDSROW + col) * 2);
            }
            #pragma unroll
            for (int ib = 0; ib < 2; ib++) {
                int n = warp_n * 32 + ib * 16 + (lane & 7) + ((lane >> 4) << 3);
                int col = kc + (lane & 8);
                uint32_t r4[4];
                ldmatrix_x4(r4, b + 2 * TILE_B + (uint32_t)(n * LDSROW + col) * 2);
                bh[ib * 2][0] = r4[0]; bh[ib * 2][1] = r4[1];
                bh[ib * 2 + 1][0] = r4[2]; bh[ib * 2 + 1][1] = r4[3];
            }
            #pragma unroll
            for (int im = 0; im < 4; im++) {
                int row = warp_m * 64 + im * 16 + (lane & 15);
                int col = kc + ((lane >> 4) << 3);
                ldmatrix_x4(al4[im], b + TILE_B + (uint32_t)(row * LDSROW + col) * 2);
            }
            // all fragments resident: 32 back-to-back MMAs
            #pragma unroll
            for (int im = 0; im < 4; im++)
                #pragma unroll
                for (int in = 0; in < 4; in++)
                    mma_16816(acc[im][in], ah4[im], bh[in]);
            #pragma unroll
            for (int im = 0; im < 4; im++)
                #pragma unroll
                for (int in = 0; in < 4; in++)
                    mma_16816(acc[im][in], al4[im], bh[in]);
        }
        __syncthreads();
    }
}

// Epilogue: clip + RMSNorm + RoPE + split-fp16 write (one head per col-block).
// khl: write lo plane only when dl != nullptr.
__device__ __forceinline__ void epi_norm_rope(
    float acc[4][4][4], char* dsm, int row0, int col0, int LD,
    const float* __restrict__ w,
    __half* __restrict__ dh, __half* __restrict__ dl) {
    const int tid = threadIdx.x;
    const int wid = tid >> 5;
    const int lane = tid & 31;
    const int warp_m = wid & 1;
    const int warp_n = wid >> 1;
    float* xs = (float*)dsm;                 // [128][132]
    float* rs = xs + 128 * 132;              // [128][4]

    #pragma unroll
    for (int im = 0; im < 4; im++) {
        #pragma unroll
        for (int half_ = 0; half_ < 2; half_++) {
            const int rl = warp_m * 64 + im * 16 + (lane >> 2) + half_ * 8;
            float ss = 0.0f;
            #pragma unroll
            for (int in = 0; in < 4; in++) {
                #pragma unroll
                for (int c = 0; c < 2; c++) {
                    float v = acc[im][in][half_ * 2 + c];
                    v = fminf(fmaxf(v, -CLIPV), CLIPV);
                    acc[im][in][half_ * 2 + c] = v;
                    xs[rl * 132 + warp_n * 32 + in * 8 + 2 * (lane & 3) + c] = v;
                    ss += v * v;
                }
            }
            ss += __shfl_xor_sync(0xffffffffu, ss, 1);
            ss += __shfl_xor_sync(0xffffffffu, ss, 2);
            if ((lane & 3) == 0) rs[rl * 4 + warp_n] = ss;
        }
    }
    __syncthreads();

    #pragma unroll
    for (int im = 0; im < 4; im++) {
        #pragma unroll
        for (int half_ = 0; half_ < 2; half_++) {
            const int rl = warp_m * 64 + im * 16 + (lane >> 2) + half_ * 8;
            const int pos = row0 + rl;
            const float sum = rs[rl * 4] + rs[rl * 4 + 1] + rs[rl * 4 + 2] + rs[rl * 4 + 3];
            const float rsig = rsqrtf(sum * (1.0f / HD) + 1e-6f);
            #pragma unroll
            for (int in = 0; in < 4; in++) {
                const int col = warp_n * 32 + in * 8 + 2 * (lane & 3);
                float o[2];
                #pragma unroll
                for (int c = 0; c < 2; c++) {
                    const int cc = col + c;
                    const float xn = acc[im][in][half_ * 2 + c] * rsig * w[cc];
                    const float xp = xs[rl * 132 + (cc ^ 64)] * rsig * w[cc ^ 64];
                    const float cs = g_cos[pos * 64 + (cc & 63)];
                    const float sn = g_sin[pos * 64 + (cc & 63)];
                    o[c] = xn * cs + ((cc < 64) ? -xp : xp) * sn;
                }
                __half2 hp = __floats2half2_rn(o[0], o[1]);
                const size_t off = (size_t)pos * LD + col0 + col;
                *(__half2*)(dh + off) = hp;
                if (dl != nullptr) {
                    __half2 lp = __floats2half2_rn(o[0] - __half2float(__low2half(hp)),
                                                   o[1] - __half2float(__high2half(hp)));
                    *(__half2*)(dl + off) = lp;
                }
            }
        }
    }
}

// Epilogue: clip + split-fp16 write (V path).
__device__ __forceinline__ void epi_split(
    float acc[4][4][4], int row0, int col0, int LD,
    __half* __restrict__ dh, __half* __restrict__ dl) {
    const int tid = threadIdx.x;
    const int wid = tid >> 5;
    const int lane = tid & 31;
    const int warp_m = wid & 1;
    const int warp_n = wid >> 1;
    #pragma unroll
    for (int im = 0; im < 4; im++) {
        #pragma unroll
        for (int half_ = 0; half_ < 2; half_++) {
            const int row = row0 + warp_m * 64 + im * 16 + (lane >> 2) + half_ * 8;
            #pragma unroll
            for (int in = 0; in < 4; in++) {
                const int col = warp_n * 32 + in * 8 + 2 * (lane & 3);
                float o[2];
                #pragma unroll
                for (int c = 0; c < 2; c++)
                    o[c] = fminf(fmaxf(acc[im][in][half_ * 2 + c], -CLIPV), CLIPV);
                __half2 hp = __floats2half2_rn(o[0], o[1]);
                __half2 lp = __floats2half2_rn(o[0] - __half2float(__low2half(hp)),
                                               o[1] - __half2float(__high2half(hp)));
                const size_t off = (size_t)row * LD + col0 + col;
                *(__half2*)(dh + off) = hp;
                *(__half2*)(dl + off) = lp;
            }
        }
    }
}

// Fused Q/K/V projection + norm/rope/split epilogues. grid (24, 16).
// K head output: hi-plane only (attention QK drops the K-lo term).
__global__ __launch_bounds__(256, 2) void qkv_gemm(const float* __restrict__ qnw,
                                                   const float* __restrict__ knw) {
    extern __shared__ char dsm[];
    const int cx = blockIdx.x;
    const int row0 = blockIdx.y << 7;
    float acc[4][4][4];
    if (cx < 16) {
        const size_t bo = (size_t)(cx << 7) * DM;
        gemm_core(g_xh + (size_t)row0 * DM, g_xl + (size_t)row0 * DM,
                  g_wqh + bo, DM, acc, dsm);
        epi_norm_rope(acc, dsm, row0, cx << 7, DM, qnw, g_qnh, g_qnl);
    } else if (cx < 20) {
        const size_t bo = (size_t)((cx - 16) << 7) * DM;
        gemm_core(g_xh + (size_t)row0 * DM, g_xl + (size_t)row0 * DM,
                  g_wkh + bo, DM, acc, dsm);
        epi_norm_rope(acc, dsm, row0, (cx - 16) << 7, KVD, knw, g_knh, nullptr);
    } else {
        const size_t bo = (size_t)((cx - 20) << 7) * DM;
        gemm_core(g_xh + (size_t)row0 * DM, g_xl + (size_t)row0 * DM,
                  g_wvh + bo, DM, acc, dsm);
        epi_split(acc, row0, (cx - 20) << 7, KVD, g_vnh, g_vnl);
    }
}

// Output projection: plain fp32 epilogue.
__global__ __launch_bounds__(256, 2) void out_gemm(float* __restrict__ out) {
    extern __shared__ char dsm[];
    const int row0 = blockIdx.y << 7;
    const int col0 = blockIdx.x << 7;
    float acc[4][4][4];
    gemm_core(g_ah + (size_t)row0 * DM, g_al + (size_t)row0 * DM,
              g_woh + (size_t)col0 * DM, DM, acc, dsm);
    const int tid = threadIdx.x;
    const int wid = tid >> 5;
    const int lane = tid & 31;
    const int warp_m = wid & 1;
    const int warp_n = wid >> 1;
    #pragma unroll
    for (int im = 0; im < 4; im++) {
        const int row = row0 + warp_m * 64 + im * 16 + (lane >> 2);
        #pragma unroll
        for (int in = 0; in < 4; in++) {
            const int col = col0 + warp_n * 32 + in * 8 + 2 * (lane & 3);
            *(float2*)(out + (size_t)row * DM + col) =
                make_float2(acc[im][in][0], acc[im][in][1]);
            *(float2*)(out + (size_t)(row + 8) * DM + col) =
                make_float2(acc[im][in][2], acc[im][in][3]);
        }
    }
}

// ---------------------------------------------------------------------------
// Tensor-core flash attention v4: 1 head per 128-thread CTA, Q (hi/lo) in
// registers, K hi-only (QK 2-pass: Qh*Kh + Ql*Kh), K double-buffered,
// V hi/lo single-buffered (FIFO wait_group pipeline), fixed-offset softmax.
// grid = (16 heads, 32 qtiles rev). Tiles: Kh0 | Kh1 | Vh | Vl.
// ---------------------------------------------------------------------------
constexpr int AST = 136;                    // smem row stride (halves), 272B aligned
constexpr int T2E = 64 * AST;               // 8704 halves per 64x128 tile
constexpr int ATTN_SMEM = 4 * T2E * 2;      // 69632 B

__global__ __launch_bounds__(128, 2) void attn_tc(const float* __restrict__ sinks) {
    extern __shared__ __half smb[];
    // tiles: [0]=Kh0 [1]=Kh1 [2]=Vh [3]=Vl  (Q staged in 0,1)
    const int h = blockIdx.x;
    const int qt = 31 - (int)blockIdx.y;     // big q-tiles first
    const int q0 = qt << 6;
    const int kvh = h >> 2;
    const int tid = threadIdx.x;
    const int wid = tid >> 5;                // warp = 16 q rows
    const int lane = tid & 31;
    const int r0 = lane >> 2;

    // ---- stage Q (hi/lo) into tiles 0,1; move to registers ----
    for (int idx = tid; idx < 1024; idx += 128) {
        int r = idx >> 4, c = idx & 15;
        const size_t go = (size_t)(q0 + r) * DM + h * HD + c * 8;
        cp_async16(smem_u32(smb + r * AST + c * 8), g_qnh + go);
        cp_async16(smem_u32(smb + T2E + r * AST + c * 8), g_qnl + go);
    }
    cp_commit();
    cp_wait<0>();
    __syncthreads();

    uint32_t aQh[8][4], aQl[8][4];
    {
        const int qrow = wid * 16 + (lane & 15);
        #pragma unroll
        for (int ks = 0; ks < 8; ks++) {
            const int qcol = ks * 16 + ((lane >> 4) << 3);
            ldmatrix_x4(aQh[ks], smem_u32(smb + qrow * AST + qcol));
            ldmatrix_x4(aQl[ks], smem_u32(smb + T2E + qrow * AST + qcol));
        }
    }
    __syncthreads();   // everyone done reading Q staging before K overwrites

    auto load_K = [&](int kt, int b) {
        const int k0 = kt << 6;
        __half* Kh = smb + b * T2E;
        for (int idx = tid; idx < 1024; idx += 128) {
            int r = idx >> 4, c = idx & 15;
            cp_async16(smem_u32(Kh + r * AST + c * 8),
                       g_knh + (size_t)(k0 + r) * KVD + kvh * HD + c * 8);
        }
    };
    auto load_V = [&](int kt) {
        const int k0 = kt << 6;
        __half* Vh = smb + 2 * T2E;
        __half* Vl = Vh + T2E;
        for (int idx = tid; idx < 1024; idx += 128) {
            int r = idx >> 4, c = idx & 15;
            const size_t go = (size_t)(k0 + r) * KVD + kvh * HD + c * 8;
            cp_async16(smem_u32(Vh + r * AST + c * 8), g_vnh + go);
            cp_async16(smem_u32(Vl + r * AST + c * 8), g_vnl + go);
        }
    };

    int lo = q0 - WIN + 1;
    if (lo < 0) lo = 0;
    const int kt_lo = lo >> 6;
    load_K(kt_lo, 0);
    cp_commit();
    load_V(kt_lo);
    cp_commit();

    float lsum[2] = {0.0f, 0.0f};
    float acc_o[16][4];
    #pragma unroll
    for (int n = 0; n < 16; n++)
        #pragma unroll
        for (int t = 0; t < 4; t++) acc_o[n][t] = 0.0f;

    for (int kt = kt_lo; kt <= qt; kt++) {
        const int b = (kt - kt_lo) & 1;
        const int k0 = kt << 6;
        const bool need_mask = (kt == qt) || (k0 < lo);
        if (kt < qt) {
            load_K(kt + 1, b ^ 1);
            cp_commit();
            cp_wait<1>();       // FIFO: forces K(kt), V(kt) complete
        } else {
            cp_wait<0>();
        }
        __syncthreads();

        __half* Kh = smb + b * T2E;
        __half* Vh = smb + 2 * T2E;
        __half* Vl = Vh + T2E;

        // ---- S = Q K^T (2 passes: Qh*Kh + Ql*Kh) ----
        float acc_s[8][4];
        #pragma unroll
        for (int j = 0; j < 8; j++)
            #pragma unroll
            for (int t = 0; t < 4; t++) acc_s[j][t] = 0.0f;

        #pragma unroll
        for (int ks = 0; ks < 8; ks++) {
            #pragma unroll
            for (int np = 0; np < 4; np++) {
                const int n = np * 16 + (lane & 7) + ((lane >> 4) << 3);
                const int col = ks * 16 + (lane & 8);
                uint32_t bh4[4];
                ldmatrix_x4(bh4, smem_u32(Kh + n * AST + col));
                mma_16816(acc_s[2 * np],     aQh[ks], bh4);
                mma_16816(acc_s[2 * np],     aQl[ks], bh4);
                mma_16816(acc_s[2 * np + 1], aQh[ks], bh4 + 2);
                mma_16816(acc_s[2 * np + 1], aQl[ks], bh4 + 2);
            }
        }

        // ---- fixed-offset softmax: p = 2^(s*C2 - M2), masked -> 0 ----
        #pragma unroll
        for (int half_ = 0; half_ < 2; half_++) {
            const int qi = q0 + wid * 16 + r0 + half_ * 8;
            float rs = 0.0f;
            if (need_mask) {
                #pragma unroll
                for (int j = 0; j < 8; j++) {
                    #pragma unroll
                    for (int c = 0; c < 2; c++) {
                        const int ki = k0 + j * 8 + 2 * (lane & 3) + c;
                        const bool ok = (ki <= qi) && (ki > qi - WIN);
                        float p = ok ? ex2(fmaf(acc_s[j][half_ * 2 + c], C2, -M2)) : 0.0f;
                        acc_s[j][half_ * 2 + c] = p;
                        rs += p;
                    }
                }
            } else {
                #pragma unroll
                for (int j = 0; j < 8; j++) {
                    #pragma unroll
                    for (int c = 0; c < 2; c++) {
                        float p = ex2(fmaf(acc_s[j][half_ * 2 + c], C2, -M2));
                        acc_s[j][half_ * 2 + c] = p;
                        rs += p;
                    }
                }
            }
            rs += __shfl_xor_sync(0xffffffffu, rs, 1);
            rs += __shfl_xor_sync(0xffffffffu, rs, 2);
            lsum[half_] += rs;
        }

        // ---- repack P into A fragments (single fp16) ----
        uint32_t aP[4][4];
        #pragma unroll
        for (int kk = 0; kk < 4; kk++) {
            #pragma unroll
            for (int t = 0; t < 4; t++) {
                const int j = 2 * kk + (t >> 1);
                const int c0 = (t & 1) * 2;
                aP[kk][t] = pack_h2(acc_s[j][c0], acc_s[j][c0 + 1]);
            }
        }

        // ---- O += P V (2 passes: P*Vh + P*Vl) ----
        #pragma unroll
        for (int kk = 0; kk < 4; kk++) {
            const int vrow = kk * 16 + (lane & 15);
            const int vcol = (lane >> 4) << 3;
            #pragma unroll
            for (int np = 0; np < 8; np++) {
                uint32_t bh4[4], bl4[4];
                ldmatrix_x4_trans(bh4, smem_u32(Vh + vrow * AST + np * 16 + vcol));
                mma_16816(acc_o[2 * np],     aP[kk], bh4);
                mma_16816(acc_o[2 * np + 1], aP[kk], bh4 + 2);
                ldmatrix_x4_trans(bl4, smem_u32(Vl + vrow * AST + np * 16 + vcol));
                mma_16816(acc_o[2 * np],     aP[kk], bl4);
                mma_16816(acc_o[2 * np + 1], aP[kk], bl4 + 2);
            }
        }
        __syncthreads();   // all warps done with V before next V load
        if (kt < qt) {
            load_V(kt + 1);
            cp_commit();
        }
    }

    // ---- sink fold + write split-fp16 output ----
    const float snk = sinks[h];
    const float sinkterm = ex2(fmaf(snk, LOG2E, -M2));
    #pragma unroll
    for (int half_ = 0; half_ < 2; half_++) {
        const float ns = 1.0f / (lsum[half_] + sinkterm);
        const int row = q0 + wid * 16 + r0 + half_ * 8;
        #pragma unroll
        for (int n = 0; n < 16; n++) {
            const float v0 = acc_o[n][half_ * 2] * ns;
            const float v1 = acc_o[n][half_ * 2 + 1] * ns;
            __half2 hp = __floats2half2_rn(v0, v1);
            __half2 lp = __floats2half2_rn(v0 - __half2float(__low2half(hp)),
                                           v1 - __half2float(__high2half(hp)));
            const size_t off = (size_t)row * DM + h * HD + n * 8 + 2 * (lane & 3);
            *(__half2*)(g_ah + off) = hp;
            *(__half2*)(g_al + off) = lp;
        }
    }
}

// ---------------------------------------------------------------------------
// Launch. qkv_gemm at my-launch idx 3 gets ncu-profiled this round.
// ---------------------------------------------------------------------------
extern "C" void kernel_launch(void* const* d_in, const int* in_sizes, int n_in,
                              void* d_out, int out_size) {
    const float* x     = (const float*)d_in[0];
    const float* w_q   = (const float*)d_in[1];
    const float* w_k   = (const float*)d_in[2];
    const float* w_v   = (const float*)d_in[3];
    const float* w_out = (const float*)d_in[4];
    const float* qnw   = (const float*)d_in[5];
    const float* knw   = (const float*)d_in[6];
    const float* sinks = (const float*)d_in[7];
    float* out = (float*)d_out;

    cudaFuncSetAttribute(qkv_gemm, cudaFuncAttributeMaxDynamicSharedMemorySize, GEMM_SMEM);
    cudaFuncSetAttribute(out_gemm, cudaFuncAttributeMaxDynamicSharedMemorySize, GEMM_SMEM);
    cudaFuncSetAttribute(attn_tc,  cudaFuncAttributeMaxDynamicSharedMemorySize, ATTN_SMEM);

    // 0: weight splits part 1 (wq, wk)
    split_w1_kernel<<<5120, 256>>>(w_q, w_k);
    // 1: weight splits part 2 (wv, wo)
    split_w2_kernel<<<5120, 256>>>(w_v, w_out);
    // 2: x split + rope tables
    prep_x_kernel<<<4608, 256>>>(x);
    // 3: fused Q/K/V projection + clip + RMSNorm + RoPE + split  (profiled slot)
    qkv_gemm<<<dim3(24, 16), 256, GEMM_SMEM>>>(qnw, knw);
    // 4: windowed flash attention + sink
    attn_tc<<<dim3(NH, 32), 128, ATTN_SMEM>>>(sinks);
    // 5: output projection
    out_gemm<<<dim3(16, 16), 256, GEMM_SMEM>>>(out);
}